// round 4
// baseline (speedup 1.0000x reference)
#include <cuda_runtime.h>
#include <cuda_bf16.h>
#include <cstdint>

// ---------------- problem constants ----------------
#define NNODES 4096          // B*n
#define NBATCH 64
#define NPG    64            // nodes per graph
#define HD     128
#define HD4    32            // HD/4
#define NE     131072        // B*epg edges (before self loops)
#define KK     52            // ceil(0.8*64)
#define NK     3328          // B*KK

#define LEN_X  (NK*HD)                    // 425984
#define OFF_A2 (LEN_X)
#define OFF_B  (OFF_A2 + NK*NK)           // 11501568
#define OFF_P  (OFF_B + NK)               // 11504896

// GEMM tiling
#define BKC 32               // K chunk
#define PITCH 17             // uint32 per 32-k row (16 + 1 pad)
#define PLANE_U32 (128*PITCH)
#define GSMEM (6*PLANE_U32*4)   // 52224 bytes

// ---------------- scratch (device globals; no allocation) ----------------
__device__ float g_deg[NNODES];
__device__ float g_dinv[NNODES];
__device__ float g_A[NBATCH*NPG*NPG];
__device__ float g_Cnt[NBATCH*NPG*NPG];
__device__ float g_S[NBATCH*NPG*NPG];
__device__ float g_tmp[NNODES*HD];
__device__ float g_xq[NNODES*HD];
__device__ float g_qt[NNODES*HD];
__device__ float g_a[2*NNODES*HD];
__device__ float g_h1[2*NNODES*2*HD];
__device__ float g_h2[2*NNODES*HD];
__device__ float g_logit[2*NNODES];
__device__ float g_f[2*NNODES];
__device__ float g_agg[NNODES*HD];
__device__ float g_P[2*NNODES*HD];
__device__ float g_xc[NNODES*HD];
__device__ float g_score[NNODES];
__device__ int   g_perm[NK];

__device__ __forceinline__ float lrelu(float v){ return v > 0.f ? v : 0.01f*v; }

// exact 3-way bf16 split (residuals are exactly representable in fp32)
__device__ __forceinline__ void split3(float a, unsigned short& h0, unsigned short& h1, unsigned short& h2){
    __nv_bfloat16 b0 = __float2bfloat16(a); float r1 = a - __bfloat162float(b0);
    __nv_bfloat16 b1 = __float2bfloat16(r1); float r2 = r1 - __bfloat162float(b1);
    __nv_bfloat16 b2 = __float2bfloat16(r2);
    h0 = __bfloat16_as_ushort(b0);
    h1 = __bfloat16_as_ushort(b1);
    h2 = __bfloat16_as_ushort(b2);
}
__device__ __forceinline__ void split2pack(float a, float b, uint32_t& p0, uint32_t& p1, uint32_t& p2){
    unsigned short a0,a1,a2,b0,b1,b2;
    split3(a, a0, a1, a2);
    split3(b, b0, b1, b2);
    p0 = (uint32_t)a0 | ((uint32_t)b0 << 16);
    p1 = (uint32_t)a1 | ((uint32_t)b1 << 16);
    p2 = (uint32_t)a2 | ((uint32_t)b2 << 16);
}

__device__ __forceinline__ void mma16816(float* d, const uint32_t* a, const uint32_t* b){
    asm volatile(
        "mma.sync.aligned.m16n8k16.row.col.f32.bf16.bf16.f32 "
        "{%0,%1,%2,%3}, {%4,%5,%6,%7}, {%8,%9}, {%0,%1,%2,%3};"
        : "+f"(d[0]), "+f"(d[1]), "+f"(d[2]), "+f"(d[3])
        : "r"(a[0]), "r"(a[1]), "r"(a[2]), "r"(a[3]), "r"(b[0]), "r"(b[1]));
}

// ---------------- HMMA GEMM ----------------
// C[z][m][n] = act( A[z] @ B[z] ); block tile 128x128, 8 warps (warp tile 64x32).
// fp32 sources split into 3 bf16 planes in smem; 6 split products {00,01,10,11,02,20}
// accumulate into one fp32 accumulator (error ~2^-26).
// FUSE=1: A row = concat section of [a, q, a-q, a*q] (each 128 wide, Ktot=512).
template<int ACT, int FUSE>
__global__ void __launch_bounds__(256) k_mgemm(
    const float* __restrict__ Asrc, long long aZ,
    const float* __restrict__ Bsrc, long long bZ,
    float* __restrict__ C, long long cZ,
    int Ktot, int Nc, int Nw,
    const float* __restrict__ q0, const float* __restrict__ q1)
{
    extern __shared__ uint32_t smu[];
    uint32_t* Ap0 = smu;
    uint32_t* Ap1 = smu + PLANE_U32;
    uint32_t* Ap2 = smu + 2*PLANE_U32;
    uint32_t* Bp0 = smu + 3*PLANE_U32;
    uint32_t* Bp1 = smu + 4*PLANE_U32;
    uint32_t* Bp2 = smu + 5*PLANE_U32;

    int t = threadIdx.x, wid = t >> 5, lane = t & 31;
    int z = blockIdx.z;
    int rowBase = blockIdx.y * 128;
    int colBase = blockIdx.x * 128;
    int warpM = (wid >> 2) * 64;
    int warpN = (wid & 3) * 32;

    const float* Az = Asrc + (size_t)z * aZ;
    const float* Q  = FUSE ? (z ? q1 : q0) : (const float*)0;
    const float* Bz = Bsrc + (size_t)z * bZ;
    C += (size_t)z * cZ;

    float acc[16][4];
#pragma unroll
    for (int i=0;i<16;i++){ acc[i][0]=0.f; acc[i][1]=0.f; acc[i][2]=0.f; acc[i][3]=0.f; }

    int chunks = Ktot / BKC;
    for (int c = 0; c < chunks; c++){
        int k0 = c * BKC;
        // ---- fill A planes: thread (r = t>>1, kh = t&1 -> 16 k) ----
        {
            int r = t >> 1, kh = t & 1;
            const float* ap; const float* qp = (const float*)0; int sec = 0;
            if (FUSE){
                sec = k0 >> 7;
                int f0 = (k0 & 127) + kh*16;
                ap = Az + (size_t)(rowBase + r) * HD + f0;
                qp = Q  + (size_t)(rowBase + r) * HD + f0;
            } else {
                ap = Az + (size_t)(rowBase + r) * (size_t)Ktot + k0 + kh*16;
            }
            float4 v[4];
#pragma unroll
            for (int i=0;i<4;i++) v[i] = *(const float4*)(ap + i*4);
            if (FUSE && sec){
#pragma unroll
                for (int i=0;i<4;i++){
                    float4 q4 = *(const float4*)(qp + i*4);
                    if (sec == 1) v[i] = q4;
                    else if (sec == 2){ v[i].x-=q4.x; v[i].y-=q4.y; v[i].z-=q4.z; v[i].w-=q4.w; }
                    else { v[i].x*=q4.x; v[i].y*=q4.y; v[i].z*=q4.z; v[i].w*=q4.w; }
                }
            }
            const float* fv = (const float*)v;
            int base = r*PITCH + kh*8;
#pragma unroll
            for (int j=0;j<8;j++){
                uint32_t p0,p1,p2;
                split2pack(fv[2*j], fv[2*j+1], p0, p1, p2);
                Ap0[base+j]=p0; Ap1[base+j]=p1; Ap2[base+j]=p2;
            }
        }
        // ---- fill B planes: B[K,N] -> Bs[n][k]; thread (n = t&127, kg = t>>7) ----
        {
            int n = t & 127, kg = t >> 7;
            __nv_bfloat16* B0h = (__nv_bfloat16*)Bp0;
            __nv_bfloat16* B1h = (__nv_bfloat16*)Bp1;
            __nv_bfloat16* B2h = (__nv_bfloat16*)Bp2;
            const float* bp = Bz + colBase + n;
            int hbase = n * (PITCH*2);
#pragma unroll
            for (int j=0;j<16;j++){
                int k = kg + 2*j;
                float xv = bp[(size_t)(k0 + k) * Nw];
                unsigned short h0,h1,h2;
                split3(xv, h0, h1, h2);
                B0h[hbase+k] = __ushort_as_bfloat16(h0);
                B1h[hbase+k] = __ushort_as_bfloat16(h1);
                B2h[hbase+k] = __ushort_as_bfloat16(h2);
            }
        }
        __syncthreads();

        // ---- MMA: products a0{b0,b1,b2}, a1{b0,b1}, a2{b0} ----
#pragma unroll
        for (int s=0; s<2; s++){
            uint32_t bf[3][4][2];
#pragma unroll
            for (int ni=0; ni<4; ni++){
                int bbase = (warpN + ni*8 + (lane>>2))*PITCH + s*8 + (lane&3);
                bf[0][ni][0]=Bp0[bbase]; bf[0][ni][1]=Bp0[bbase+4];
                bf[1][ni][0]=Bp1[bbase]; bf[1][ni][1]=Bp1[bbase+4];
                bf[2][ni][0]=Bp2[bbase]; bf[2][ni][1]=Bp2[bbase+4];
            }
#pragma unroll
            for (int apl=0; apl<3; apl++){
                const uint32_t* As = (apl==0)?Ap0:((apl==1)?Ap1:Ap2);
                uint32_t af[4][4];
#pragma unroll
                for (int mi=0; mi<4; mi++){
                    int abase = (warpM + mi*16 + (lane>>2))*PITCH + s*8 + (lane&3);
                    af[mi][0]=As[abase];
                    af[mi][1]=As[abase+8*PITCH];
                    af[mi][2]=As[abase+4];
                    af[mi][3]=As[abase+8*PITCH+4];
                }
                int nb = (apl==0)?3:((apl==1)?2:1);
#pragma unroll
                for (int bpl=0; bpl<3; bpl++){
                    if (bpl >= nb) break;
#pragma unroll
                    for (int mi=0; mi<4; mi++)
#pragma unroll
                        for (int ni=0; ni<4; ni++)
                            mma16816(acc[mi*4+ni], af[mi], bf[bpl][ni]);
                }
            }
        }
        __syncthreads();
    }

    // ---- epilogue ----
#pragma unroll
    for (int mi=0; mi<4; mi++){
#pragma unroll
        for (int ni=0; ni<4; ni++){
            float* d = acc[mi*4+ni];
            if (ACT){ d[0]=lrelu(d[0]); d[1]=lrelu(d[1]); d[2]=lrelu(d[2]); d[3]=lrelu(d[3]); }
            int r0 = rowBase + warpM + mi*16 + (lane>>2);
            int c0 = colBase + warpN + ni*8 + (lane&3)*2;
            *(float2*)(C + (size_t)r0*Nc + c0)       = make_float2(d[0], d[1]);
            *(float2*)(C + (size_t)(r0+8)*Nc + c0)   = make_float2(d[2], d[3]);
        }
    }
}

// ---------------- setup kernels ----------------
__global__ void k_init(){
    int i = blockIdx.x*blockDim.x + threadIdx.x;
    if (i < NBATCH*NPG*NPG){ g_A[i]=0.f; g_Cnt[i]=0.f; }
    if (i < NNODES) g_deg[i] = 1.0f;
}

__global__ void k_deg(const int* __restrict__ col, const float* __restrict__ w){
    int e = blockIdx.x*blockDim.x + threadIdx.x;
    if (e < NE) atomicAdd(&g_deg[col[e]], w[e]);
}

__global__ void k_dinv(){
    int i = blockIdx.x*blockDim.x + threadIdx.x;
    if (i < NNODES) g_dinv[i] = rsqrtf(g_deg[i]);
}

__global__ void k_build(const int* __restrict__ row, const int* __restrict__ col,
                        const float* __restrict__ w){
    int e = blockIdx.x*blockDim.x + threadIdx.x;
    if (e < NE){
        int r = row[e], c = col[e];
        float ew = g_dinv[r]*w[e]*g_dinv[c];
        int b = r >> 6;
        int idx = b*NPG*NPG + (r&63)*NPG + (c&63);
        atomicAdd(&g_A[idx], ew);
        atomicAdd(&g_Cnt[idx], 1.0f);
    } else if (e < NE + NNODES){
        int i = e - NE;
        int b = i >> 6, l = i & 63;
        int idx = b*NPG*NPG + l*NPG + l;
        atomicAdd(&g_A[idx], g_dinv[i]*g_dinv[i]);
        atomicAdd(&g_Cnt[idx], 1.0f);
    }
}

__global__ void k_qt(const float4* __restrict__ tx4){
    int i = blockIdx.x*blockDim.x + threadIdx.x;
    int node = i >> 5, f4 = i & 31;
    ((float4*)g_qt)[i] = tx4[(node>>6)*HD4 + f4];
}

__global__ void k_hop(const float4* __restrict__ vin, float4* __restrict__ vout){
    int b = blockIdx.x, t = threadIdx.x;
    __shared__ float sA[NPG*NPG];
    for (int i=t; i<NPG*NPG; i+=256) sA[i] = g_A[b*NPG*NPG+i];
    __syncthreads();
    int tx = t & 31, ty = t >> 5;
    for (int cc=0; cc<8; cc++){
        int c = ty*8+cc;
        float4 acc = make_float4(0.f,0.f,0.f,0.f);
        for (int r=0; r<NPG; r++){
            float a = sA[r*NPG+c];
            float4 v = vin[(b*NPG+r)*HD4 + tx];
            acc.x += a*v.x; acc.y += a*v.y; acc.z += a*v.z; acc.w += a*v.w;
        }
        vout[(b*NPG+c)*HD4 + tx] = acc;
    }
}

// ---------------- attention helpers ----------------
__global__ void k_w3(const float* __restrict__ W3, int base){
    int gt = blockIdx.x*blockDim.x + threadIdx.x;
    int warp = gt >> 5, lane = gt & 31;
    if (warp >= 2*NNODES) return;
    int z = warp >> 12;
    const float* w = W3 + (size_t)(base+z)*HD;
    const float* h = g_h2 + (size_t)warp*HD;
    float s = 0.f;
#pragma unroll
    for (int k=0; k<4; k++) s += h[lane+32*k]*w[lane+32*k];
    for (int o=16; o; o>>=1) s += __shfl_xor_sync(0xffffffffu, s, o);
    if (lane == 0) g_logit[warp] = lrelu(s);
}

__global__ void k_softmax64(const float* __restrict__ in, float* __restrict__ out){
    __shared__ float red[64];
    int b = blockIdx.x, t = threadIdx.x;
    float v = in[b*64+t];
    red[t] = v; __syncthreads();
    for (int o=32; o>0; o>>=1){ if (t<o) red[t] = fmaxf(red[t], red[t+o]); __syncthreads(); }
    float m = red[0];
    __syncthreads();
    float e = expf(v - m);
    red[t] = e; __syncthreads();
    for (int o=32; o>0; o>>=1){ if (t<o) red[t] += red[t+o]; __syncthreads(); }
    out[b*64+t] = e / red[0];
}

__global__ void k_score(){
    __shared__ float red[64];
    int b = blockIdx.x, t = threadIdx.x;
    float v = g_f[b*64+t] + g_f[NNODES + b*64+t];
    red[t] = v; __syncthreads();
    for (int o=32; o>0; o>>=1){ if (t<o) red[t] = fmaxf(red[t], red[t+o]); __syncthreads(); }
    float m = red[0];
    __syncthreads();
    float e = expf(v - m);
    red[t] = e; __syncthreads();
    for (int o=32; o>0; o>>=1){ if (t<o) red[t] += red[t+o]; __syncthreads(); }
    g_score[b*64+t] = e / red[0];
}

// ---------------- edge softmax + S + agg ----------------
__global__ void k_edge(const float* __restrict__ x){
    int b = blockIdx.x, t = threadIdx.x;
    __shared__ float sC[NPG*NPG];
    __shared__ float sL[NPG*NPG];
    __shared__ float sf1[NPG], sf2[NPG], sm_[NPG], sden[NPG];
    for (int i=t; i<NPG*NPG; i+=256) sC[i] = g_Cnt[b*NPG*NPG+i];
    if (t < NPG){ sf1[t] = g_f[b*NPG+t]; sf2[t] = g_f[NNODES + b*NPG+t]; }
    __syncthreads();
    for (int i=t; i<NPG*NPG; i+=256){
        int r = i>>6, c = i&63;
        sL[i] = (sC[i] > 0.f) ? lrelu(sf1[c] + sf2[r]) : -1e30f;
    }
    __syncthreads();
    if (t < NPG){
        float m = -1e30f;
        for (int r=0; r<NPG; r++) m = fmaxf(m, sL[r*NPG+t]);
        float den = 0.f;
        for (int r=0; r<NPG; r++){
            float cc = sC[r*NPG+t];
            if (cc > 0.f) den += cc*expf(sL[r*NPG+t]-m);
        }
        sm_[t] = m; sden[t] = den;
    }
    __syncthreads();
    for (int i=t; i<NPG*NPG; i+=256){
        int c = i & 63;
        float cc = sC[i];
        float s = (cc > 0.f) ? cc*expf(sL[i]-sm_[c])/sden[c] : 0.f;
        sL[i] = s;
        g_S[b*NPG*NPG+i] = s;
    }
    __syncthreads();
    const float4* X4 = (const float4*)x;
    float4* AG4 = (float4*)g_agg;
    int tx = t & 31, ty = t >> 5;
    for (int cc=0; cc<8; cc++){
        int c = ty*8+cc;
        float4 acc = make_float4(0.f,0.f,0.f,0.f);
        for (int r=0; r<NPG; r++){
            float s = sL[r*NPG+c];
            float4 v = X4[(b*NPG+r)*HD4 + tx];
            acc.x += s*v.x; acc.y += s*v.y; acc.z += s*v.z; acc.w += s*v.w;
        }
        AG4[(b*NPG+c)*HD4 + tx] = acc;
    }
}

__global__ void k_xc(const float* __restrict__ x){
    int i = blockIdx.x*blockDim.x + threadIdx.x;
    if (i < NNODES*HD){
        float xv = x[i];
        float v0 = lrelu(xv + g_P[i]);
        float v1 = lrelu(xv + g_P[NNODES*HD + i]);
        g_xc[i] = 0.5f*(v0+v1);
    }
}

// ---------------- top-k + outputs ----------------
__global__ void k_topk_out(const float* __restrict__ x, float* __restrict__ out){
    __shared__ float s[64];
    __shared__ int lp[KK];
    int b = blockIdx.x, t = threadIdx.x;
    if (t < 64) s[t] = g_score[b*64+t];
    __syncthreads();
    if (t < 64){
        float v = s[t];
        int rank = 0;
        for (int j=0; j<64; j++){
            float u = s[j];
            rank += (u > v) || (u == v && j < t);
        }
        if (rank < KK){
            lp[rank] = t;
            g_perm[b*KK+rank] = b*64+t;
            out[OFF_B + b*KK+rank] = (float)b;
            out[OFF_P + b*KK+rank] = (float)(b*64+t);
        }
    }
    __syncthreads();
    const float4* x4 = (const float4*)x;
    float4* o4 = (float4*)out;
    for (int i=t; i<KK*32; i+=256){
        int r = i >> 5, f = i & 31;
        int p = lp[r];
        float sc = s[p];
        float4 v = x4[(b*64+p)*32 + f];
        o4[(size_t)(b*KK+r)*32 + f] = make_float4(v.x*sc, v.y*sc, v.z*sc, v.w*sc);
    }
}

// ---------------- A2 block triple-product ----------------
__global__ void k_A2(float* __restrict__ out){
    int b = blockIdx.x, t = threadIdx.x;
    __shared__ float sA[NPG*NPG];
    __shared__ float sS[NPG*NPG];
    __shared__ float sU[NPG*KK];
    __shared__ int   sI[KK];
    for (int i=t; i<NPG*NPG; i+=256){ sA[i] = g_A[b*NPG*NPG+i]; sS[i] = g_S[b*NPG*NPG+i]; }
    if (t < KK) sI[t] = g_perm[b*KK+t] - b*NPG;
    __syncthreads();
    for (int idx=t; idx<NPG*KK; idx+=256){
        int r = idx / KK, j = idx - r*KK;
        int pj = sI[j];
        float acc = 0.f;
        for (int c=0; c<NPG; c++) acc += sA[r*NPG+c]*sS[c*NPG+pj];
        sU[idx] = acc;
    }
    __syncthreads();
    for (int idx=t; idx<KK*KK; idx+=256){
        int i2 = idx / KK, j = idx - i2*KK;
        int pi = sI[i2];
        float acc = 0.f;
        for (int r=0; r<NPG; r++) acc += sS[r*NPG+pi]*sU[r*KK+j];
        float v = (i2 == j) ? 1.0f : acc;
        out[(size_t)OFF_A2 + (size_t)(b*KK+i2)*NK + (b*KK+j)] = v;
    }
}

// ---------------- host-side attention pipeline ----------------
static void launch_attention(int base, const float* kv, const float* q0, const float* q1,
                             const float* Wk, const float* W1, const float* W2, const float* W3,
                             float* p_a, float* p_h1, float* p_h2,
                             float* p_logit, float* p_f)
{
    // a[z] = kv @ Wk[base+z]
    k_mgemm<0,0><<<dim3(1,32,2),256,GSMEM>>>(kv, 0LL,
        Wk + (long long)base*HD*HD, (long long)HD*HD,
        p_a, (long long)NNODES*HD, HD, HD, HD, nullptr, nullptr);
    // h1 = lrelu(concat[a,q,a-q,a*q] @ W1[base+z])
    k_mgemm<1,1><<<dim3(2,32,2),256,GSMEM>>>(p_a, (long long)NNODES*HD,
        W1 + (long long)base*512*256, 512LL*256,
        p_h1, (long long)NNODES*256, 512, 256, 256, q0, q1);
    // h2 = lrelu(h1 @ W2[base+z])
    k_mgemm<1,0><<<dim3(1,32,2),256,GSMEM>>>(p_h1, (long long)NNODES*256,
        W2 + (long long)base*256*128, 256LL*128,
        p_h2, (long long)NNODES*HD, 256, HD, HD, nullptr, nullptr);
    k_w3<<<(2*NNODES*32)/256,256>>>(W3, base);
    k_softmax64<<<2*NBATCH,64>>>(p_logit, p_f);
}

extern "C" void kernel_launch(void* const* d_in, const int* in_sizes, int n_in,
                              void* d_out, int out_size)
{
    (void)in_sizes; (void)n_in; (void)out_size;
    const float* x    = (const float*)d_in[0];
    const int*   ei   = (const int*)  d_in[1];
    const float* ew   = (const float*)d_in[2];
    const float* txg  = (const float*)d_in[3];
    const float* Wk   = (const float*)d_in[5];
    const float* W1   = (const float*)d_in[6];
    const float* W2   = (const float*)d_in[7];
    const float* W3   = (const float*)d_in[8];
    const float* linW = (const float*)d_in[9];
    float* out = (float*)d_out;
    const int* row = ei;
    const int* col = ei + NE;

    cudaFuncSetAttribute(k_mgemm<0,0>, cudaFuncAttributeMaxDynamicSharedMemorySize, GSMEM);
    cudaFuncSetAttribute(k_mgemm<1,0>, cudaFuncAttributeMaxDynamicSharedMemorySize, GSMEM);
    cudaFuncSetAttribute(k_mgemm<1,1>, cudaFuncAttributeMaxDynamicSharedMemorySize, GSMEM);

    float *p_tmp,*p_xq,*p_qt,*p_a,*p_h1,*p_h2,*p_logit,*p_f,*p_agg,*p_P,*p_xc;
    cudaGetSymbolAddress((void**)&p_tmp,   g_tmp);
    cudaGetSymbolAddress((void**)&p_xq,    g_xq);
    cudaGetSymbolAddress((void**)&p_qt,    g_qt);
    cudaGetSymbolAddress((void**)&p_a,     g_a);
    cudaGetSymbolAddress((void**)&p_h1,    g_h1);
    cudaGetSymbolAddress((void**)&p_h2,    g_h2);
    cudaGetSymbolAddress((void**)&p_logit, g_logit);
    cudaGetSymbolAddress((void**)&p_f,     g_f);
    cudaGetSymbolAddress((void**)&p_agg,   g_agg);
    cudaGetSymbolAddress((void**)&p_P,     g_P);
    cudaGetSymbolAddress((void**)&p_xc,    g_xc);

    // graph setup
    k_init<<<1024,256>>>();
    k_deg<<<NE/256,256>>>(col, ew);
    k_dinv<<<NNODES/256,256>>>();
    k_build<<<(NE+NNODES)/256,256>>>(row, col, ew);
    k_qt<<<(NNODES*HD4)/256,256>>>((const float4*)txg);

    // x_q = hop(hop(x))
    k_hop<<<NBATCH,256>>>((const float4*)x, (float4*)p_tmp);
    k_hop<<<NBATCH,256>>>((const float4*)p_tmp, (float4*)p_xq);

    // f1 = att(x, x_q, W[0]); f2 = att(x, qt, W[1])
    launch_attention(0, x, p_xq, p_qt, Wk, W1, W2, W3, p_a, p_h1, p_h2, p_logit, p_f);

    // edge softmax -> S, agg
    k_edge<<<NBATCH,256>>>(x);

    // P[h] = agg @ lin_W[h]
    k_mgemm<0,0><<<dim3(1,32,2),256,GSMEM>>>(p_agg, 0LL,
        linW, (long long)HD*HD,
        p_P, (long long)NNODES*HD, HD, HD, HD, nullptr, nullptr);
    k_xc<<<(NNODES*HD)/256,256>>>(x);

    // x_q2 = hop(hop(x_c))
    k_hop<<<NBATCH,256>>>((const float4*)p_xc, (float4*)p_tmp);
    k_hop<<<NBATCH,256>>>((const float4*)p_tmp, (float4*)p_xq);

    // g1 = att(x_c, x_q2, W[2]); g2 = att(x_c, qt, W[3])
    launch_attention(2, p_xc, p_xq, p_qt, Wk, W1, W2, W3, p_a, p_h1, p_h2, p_logit, p_f);

    // cluster_score = softmax_batch(g1+g2)
    k_score<<<NBATCH,64>>>();

    // top-k + outputs
    k_topk_out<<<NBATCH,256>>>(x, out);
    cudaMemsetAsync(out + OFF_A2, 0, (size_t)NK*NK*sizeof(float));
    k_A2<<<NBATCH,256>>>(out);
}

// round 6
// speedup vs baseline: 1.3052x; 1.3052x over previous
#include <cuda_runtime.h>
#include <cuda_bf16.h>
#include <cstdint>

// ---------------- problem constants ----------------
#define NNODES 4096
#define NBATCH 64
#define NPG    64
#define HD     128
#define HD4    32
#define NE     131072
#define KK     52
#define NK     3328

#define LEN_X  (NK*HD)
#define OFF_A2 (LEN_X)
#define OFF_B  (OFF_A2 + NK*NK)
#define OFF_P  (OFF_B + NK)

// GEMM smem: 3 planes x 128 rows x 20 u32 (40 halfs, 32 used) per side
#define ROWU 20
#define PLU  (128*ROWU)          // 2560 u32 per plane
#define GSMEM (6*PLU*4)          // 61440 bytes

// ---------------- scratch ----------------
__device__ float g_deg[NNODES];
__device__ float g_dinv[NNODES];
__device__ float g_A[NBATCH*NPG*NPG];
__device__ float g_Cnt[NBATCH*NPG*NPG];
__device__ float g_S[NBATCH*NPG*NPG];
__device__ float g_tmp[NNODES*HD];
__device__ float g_xq[NNODES*HD];
__device__ float g_qt[NNODES*HD];
__device__ float g_h2[2*NNODES*HD];
__device__ float g_f[2*NNODES];
__device__ float g_P[2*NNODES*HD];
__device__ int   g_perm[NK];

// bf16 split planes (plane-major), 16B-aligned for uint4 access
__device__ __align__(16) __nv_bfloat16 g_XP  [3*NNODES*HD];
__device__ __align__(16) __nv_bfloat16 g_xcP [3*NNODES*HD];
__device__ __align__(16) __nv_bfloat16 g_aggP[3*NNODES*HD];
__device__ __align__(16) __nv_bfloat16 g_WkP [3*4*128*128];
__device__ __align__(16) __nv_bfloat16 g_W1P [3*4*256*512];
__device__ __align__(16) __nv_bfloat16 g_W2P [3*4*128*256];
__device__ __align__(16) __nv_bfloat16 g_LWP [3*2*128*128];
__device__ __align__(16) __nv_bfloat16 g_h0P [3*2*NNODES*512];
__device__ __align__(16) __nv_bfloat16 g_h1P [3*2*NNODES*256];

__device__ __forceinline__ float lrelu(float v){ return v > 0.f ? v : 0.01f*v; }

// exact 3-way bf16 split
__device__ __forceinline__ void split3(float a, unsigned short& h0, unsigned short& h1, unsigned short& h2){
    __nv_bfloat16 b0 = __float2bfloat16(a); float r1 = a - __bfloat162float(b0);
    __nv_bfloat16 b1 = __float2bfloat16(r1); float r2 = r1 - __bfloat162float(b1);
    __nv_bfloat16 b2 = __float2bfloat16(r2);
    h0 = __bfloat16_as_ushort(b0);
    h1 = __bfloat16_as_ushort(b1);
    h2 = __bfloat16_as_ushort(b2);
}
__device__ __forceinline__ void split2pack(float a, float b, uint32_t& p0, uint32_t& p1, uint32_t& p2){
    unsigned short a0,a1,a2,b0,b1,b2;
    split3(a, a0, a1, a2);
    split3(b, b0, b1, b2);
    p0 = (uint32_t)a0 | ((uint32_t)b0 << 16);
    p1 = (uint32_t)a1 | ((uint32_t)b1 << 16);
    p2 = (uint32_t)a2 | ((uint32_t)b2 << 16);
}

__device__ __forceinline__ void mma16816(float* d, const uint32_t* a, const uint32_t* b){
    asm volatile(
        "mma.sync.aligned.m16n8k16.row.col.f32.bf16.bf16.f32 "
        "{%0,%1,%2,%3}, {%4,%5,%6,%7}, {%8,%9}, {%0,%1,%2,%3};"
        : "+f"(d[0]), "+f"(d[1]), "+f"(d[2]), "+f"(d[3])
        : "r"(a[0]), "r"(a[1]), "r"(a[2]), "r"(a[3]), "r"(b[0]), "r"(b[1]));
}

// ---------------- pre-split GEMM ----------------
// A planes [3][z][M][K] bf16 (strides aP plane, aZ z); B planes [3][z][N][K] (n-major).
// EPI: 0=fp32 store, 1=lrelu fp32, 2=lrelu+split->planes, 3=H0 concat splits.
template<int EPI>
__global__ void __launch_bounds__(256) k_pgemm(
    const __nv_bfloat16* __restrict__ AP, long long aZ, long long aP,
    const __nv_bfloat16* __restrict__ BP, long long bZ, long long bP,
    int Ktot, int Nc,
    float* __restrict__ Cout, long long cZ,
    __nv_bfloat16* __restrict__ OP, long long oZ, long long oP,
    const float* __restrict__ q0, const float* __restrict__ q1)
{
    extern __shared__ uint32_t smu[];
    int t = threadIdx.x, wid = t >> 5, lane = t & 31;
    int z = blockIdx.z;
    int rowBase = blockIdx.y * 128;
    int colBase = blockIdx.x * 128;
    int warpM = (wid >> 2) * 64;
    int warpN = (wid & 3) * 32;

    float acc[16][4];
#pragma unroll
    for (int i=0;i<16;i++){ acc[i][0]=0.f; acc[i][1]=0.f; acc[i][2]=0.f; acc[i][3]=0.f; }

    int chunks = Ktot >> 5;
    int r = t >> 1, kh = t & 1;
    for (int c = 0; c < chunks; c++){
        int k0 = c << 5;
#pragma unroll
        for (int p=0; p<3; p++){
            const __nv_bfloat16* as = AP + (size_t)p*aP + (size_t)z*aZ + (size_t)(rowBase+r)*Ktot + k0 + kh*16;
            uint4 v0 = *(const uint4*)as;
            uint4 v1 = *(const uint4*)(as+8);
            uint32_t* d = smu + p*PLU + r*ROWU + kh*8;
            d[0]=v0.x; d[1]=v0.y; d[2]=v0.z; d[3]=v0.w;
            d[4]=v1.x; d[5]=v1.y; d[6]=v1.z; d[7]=v1.w;
            const __nv_bfloat16* bs = BP + (size_t)p*bP + (size_t)z*bZ + (size_t)(colBase+r)*Ktot + k0 + kh*16;
            uint4 w0 = *(const uint4*)bs;
            uint4 w1 = *(const uint4*)(bs+8);
            uint32_t* db = smu + (3+p)*PLU + r*ROWU + kh*8;
            db[0]=w0.x; db[1]=w0.y; db[2]=w0.z; db[3]=w0.w;
            db[4]=w1.x; db[5]=w1.y; db[6]=w1.z; db[7]=w1.w;
        }
        __syncthreads();

#pragma unroll
        for (int s=0; s<2; s++){
            uint32_t bf[3][4][2];
#pragma unroll
            for (int ni=0; ni<4; ni++){
                int bbase = (warpN + ni*8 + (lane>>2))*ROWU + s*8 + (lane&3);
                bf[0][ni][0]=smu[3*PLU+bbase]; bf[0][ni][1]=smu[3*PLU+bbase+4];
                bf[1][ni][0]=smu[4*PLU+bbase]; bf[1][ni][1]=smu[4*PLU+bbase+4];
                bf[2][ni][0]=smu[5*PLU+bbase]; bf[2][ni][1]=smu[5*PLU+bbase+4];
            }
#pragma unroll
            for (int apl=0; apl<3; apl++){
                const uint32_t* As = smu + apl*PLU;
                uint32_t af[4][4];
#pragma unroll
                for (int mi=0; mi<4; mi++){
                    int abase = (warpM + mi*16 + (lane>>2))*ROWU + s*8 + (lane&3);
                    af[mi][0]=As[abase];
                    af[mi][1]=As[abase+8*ROWU];
                    af[mi][2]=As[abase+4];
                    af[mi][3]=As[abase+8*ROWU+4];
                }
                int nb = (apl==0)?3:((apl==1)?2:1);
#pragma unroll
                for (int bpl=0; bpl<3; bpl++){
                    if (bpl >= nb) break;
#pragma unroll
                    for (int mi=0; mi<4; mi++)
#pragma unroll
                        for (int ni=0; ni<4; ni++)
                            mma16816(acc[mi*4+ni], af[mi], bf[bpl][ni]);
                }
            }
        }
        __syncthreads();
    }

    // ---- epilogue ----
#pragma unroll
    for (int mi=0; mi<4; mi++){
#pragma unroll
        for (int ni=0; ni<4; ni++){
            float* d = acc[mi*4+ni];
            int r0 = rowBase + warpM + mi*16 + (lane>>2);
            int c0 = colBase + warpN + ni*8 + (lane&3)*2;
            if (EPI == 0 || EPI == 1){
                if (EPI == 1){ d[0]=lrelu(d[0]); d[1]=lrelu(d[1]); d[2]=lrelu(d[2]); d[3]=lrelu(d[3]); }
                float* cp = Cout + (size_t)z*cZ;
                *(float2*)(cp + (size_t)r0*Nc + c0)     = make_float2(d[0], d[1]);
                *(float2*)(cp + (size_t)(r0+8)*Nc + c0) = make_float2(d[2], d[3]);
            } else if (EPI == 2){
#pragma unroll
                for (int qi=0; qi<2; qi++){
                    int row = r0 + qi*8;
                    float da = lrelu(d[qi*2]), db = lrelu(d[qi*2+1]);
                    uint32_t p0,p1,p2;
                    split2pack(da, db, p0, p1, p2);
                    size_t off = (size_t)z*oZ + (size_t)row*Nc + c0;
                    *(uint32_t*)(OP + off)        = p0;
                    *(uint32_t*)(OP + oP + off)   = p1;
                    *(uint32_t*)(OP + 2*oP + off) = p2;
                }
            } else {   // EPI == 3: h0 concat
                const float* q = z ? q1 : q0;
#pragma unroll
                for (int qi=0; qi<2; qi++){
                    int row = r0 + qi*8;
                    float av = d[qi*2], bv = d[qi*2+1];
                    float qa = q[(size_t)row*128 + c0];
                    float qb = q[(size_t)row*128 + c0 + 1];
                    float sa[4] = {av, qa, av-qa, av*qa};
                    float sb[4] = {bv, qb, bv-qb, bv*qb};
#pragma unroll
                    for (int sec=0; sec<4; sec++){
                        uint32_t p0,p1,p2;
                        split2pack(sa[sec], sb[sec], p0, p1, p2);
                        size_t off = (size_t)z*oZ + (size_t)row*512 + sec*128 + c0;
                        *(uint32_t*)(OP + off)        = p0;
                        *(uint32_t*)(OP + oP + off)   = p1;
                        *(uint32_t*)(OP + 2*oP + off) = p2;
                    }
                }
            }
        }
    }
}

// ---------------- prep: split weights (+transpose), split x, build qt ----------------
#define PREP_WK   65536
#define PREP_W1   (PREP_WK + 524288)
#define PREP_W2   (PREP_W1 + 131072)
#define PREP_LW   (PREP_W2 + 32768)
#define PREP_X    (PREP_LW + 524288)
#define PREP_QT   (PREP_X + 524288)

__global__ void k_prep(const float* __restrict__ Wk, const float* __restrict__ W1,
                       const float* __restrict__ W2, const float* __restrict__ LW,
                       const float* __restrict__ x, const float* __restrict__ txg)
{
    int i = blockIdx.x*blockDim.x + threadIdx.x;
    if (i >= PREP_QT) return;
    unsigned short h0,h1,h2;
    if (i < PREP_WK){
        int z = i >> 14, rem = i & 16383, k = rem >> 7, n = rem & 127;
        split3(Wk[i], h0, h1, h2);
        size_t d = (size_t)(z*128 + n)*128 + k;
        g_WkP[d] = __ushort_as_bfloat16(h0);
        g_WkP[4*16384 + d] = __ushort_as_bfloat16(h1);
        g_WkP[8*16384 + d] = __ushort_as_bfloat16(h2);
    } else if (i < PREP_W1){
        int j = i - PREP_WK;
        int z = j >> 17, rem = j & 131071, k = rem >> 8, n = rem & 255;
        split3(W1[j], h0, h1, h2);
        size_t d = (size_t)(z*256 + n)*512 + k;
        g_W1P[d] = __ushort_as_bfloat16(h0);
        g_W1P[4*131072 + d] = __ushort_as_bfloat16(h1);
        g_W1P[(size_t)8*131072 + d] = __ushort_as_bfloat16(h2);
    } else if (i < PREP_W2){
        int j = i - PREP_W1;
        int z = j >> 15, rem = j & 32767, k = rem >> 7, n = rem & 127;
        split3(W2[j], h0, h1, h2);
        size_t d = (size_t)(z*128 + n)*256 + k;
        g_W2P[d] = __ushort_as_bfloat16(h0);
        g_W2P[4*32768 + d] = __ushort_as_bfloat16(h1);
        g_W2P[8*32768 + d] = __ushort_as_bfloat16(h2);
    } else if (i < PREP_LW){
        int j = i - PREP_W2;
        int z = j >> 14, rem = j & 16383, k = rem >> 7, n = rem & 127;
        split3(LW[j], h0, h1, h2);
        size_t d = (size_t)(z*128 + n)*128 + k;
        g_LWP[d] = __ushort_as_bfloat16(h0);
        g_LWP[2*16384 + d] = __ushort_as_bfloat16(h1);
        g_LWP[4*16384 + d] = __ushort_as_bfloat16(h2);
    } else if (i < PREP_X){
        int j = i - PREP_LW;
        split3(x[j], h0, h1, h2);
        g_XP[j] = __ushort_as_bfloat16(h0);
        g_XP[NNODES*HD + j] = __ushort_as_bfloat16(h1);
        g_XP[2*NNODES*HD + j] = __ushort_as_bfloat16(h2);
    } else {
        int j = i - PREP_X;
        g_qt[j] = txg[((j >> 13) << 7) | (j & 127)];
    }
}

// ---------------- setup kernels ----------------
__global__ void k_init(){
    int i = blockIdx.x*blockDim.x + threadIdx.x;
    if (i < NBATCH*NPG*NPG){ g_A[i]=0.f; g_Cnt[i]=0.f; }
    if (i < NNODES) g_deg[i] = 1.0f;
}
__global__ void k_deg(const int* __restrict__ col, const float* __restrict__ w){
    int e = blockIdx.x*blockDim.x + threadIdx.x;
    if (e < NE) atomicAdd(&g_deg[col[e]], w[e]);
}
__global__ void k_dinv(){
    int i = blockIdx.x*blockDim.x + threadIdx.x;
    if (i < NNODES) g_dinv[i] = rsqrtf(g_deg[i]);
}
__global__ void k_build(const int* __restrict__ row, const int* __restrict__ col,
                        const float* __restrict__ w){
    int e = blockIdx.x*blockDim.x + threadIdx.x;
    if (e < NE){
        int r = row[e], c = col[e];
        float ew = g_dinv[r]*w[e]*g_dinv[c];
        int b = r >> 6;
        int idx = b*NPG*NPG + (r&63)*NPG + (c&63);
        atomicAdd(&g_A[idx], ew);
        atomicAdd(&g_Cnt[idx], 1.0f);
    } else if (e < NE + NNODES){
        int i = e - NE;
        int b = i >> 6, l = i & 63;
        int idx = b*NPG*NPG + l*NPG + l;
        atomicAdd(&g_A[idx], g_dinv[i]*g_dinv[i]);
        atomicAdd(&g_Cnt[idx], 1.0f);
    }
}

__global__ void k_hop(const float4* __restrict__ vin, float4* __restrict__ vout){
    int b = blockIdx.x, t = threadIdx.x;
    __shared__ float sA[NPG*NPG];
    for (int i=t; i<NPG*NPG; i+=256) sA[i] = g_A[b*NPG*NPG+i];
    __syncthreads();
    int tx = t & 31, ty = t >> 5;
    for (int cc=0; cc<8; cc++){
        int c = ty*8+cc;
        float4 acc = make_float4(0.f,0.f,0.f,0.f);
        for (int r=0; r<NPG; r++){
            float a = sA[r*NPG+c];
            float4 v = vin[(b*NPG+r)*HD4 + tx];
            acc.x += a*v.x; acc.y += a*v.y; acc.z += a*v.z; acc.w += a*v.w;
        }
        vout[(b*NPG+c)*HD4 + tx] = acc;
    }
}

// ---------------- w3 dot + batch softmax (merged; all barriers full-scope) ----------------
__global__ void k_w3s(const float* __restrict__ W3, int base){
    __shared__ float sw[128];
    __shared__ float sl[64];
    __shared__ float red[64];
    int zb = blockIdx.x;
    int z = zb >> 6, b = zb & 63;
    int t = threadIdx.x;
    if (t < 128) sw[t] = W3[(size_t)(base+z)*128 + t];
    __syncthreads();
    int node = t >> 2, part = t & 3;
    const float* h = g_h2 + (size_t)(z*NNODES + b*64 + node)*128 + part*32;
    const float* w = sw + part*32;
    float s = 0.f;
#pragma unroll
    for (int j=0; j<32; j++) s += h[j]*w[j];
    s += __shfl_xor_sync(0xffffffffu, s, 1);
    s += __shfl_xor_sync(0xffffffffu, s, 2);
    if (part == 0) sl[node] = lrelu(s);
    __syncthreads();
    // softmax over sl[0..63]; barriers at full-block scope
    if (t < 64) red[t] = sl[t];
    __syncthreads();
    for (int o=32; o>0; o>>=1){ if (t<o) red[t] = fmaxf(red[t], red[t+o]); __syncthreads(); }
    float m = red[0];
    __syncthreads();
    if (t < 64){ float e = expf(sl[t] - m); sl[t] = e; red[t] = e; }
    __syncthreads();
    for (int o=32; o>0; o>>=1){ if (t<o) red[t] += red[t+o]; __syncthreads(); }
    if (t < 64) g_f[z*NNODES + b*64 + t] = sl[t] / red[0];
}

// ---------------- edge softmax + S + agg planes ----------------
__global__ void k_edge(const float* __restrict__ x){
    int b = blockIdx.x, t = threadIdx.x;
    __shared__ float sC[NPG*NPG];
    __shared__ float sL[NPG*NPG];
    __shared__ float sf1[NPG], sf2[NPG], sm_[NPG], sden[NPG];
    for (int i=t; i<NPG*NPG; i+=256) sC[i] = g_Cnt[b*NPG*NPG+i];
    if (t < NPG){ sf1[t] = g_f[b*NPG+t]; sf2[t] = g_f[NNODES + b*NPG+t]; }
    __syncthreads();
    for (int i=t; i<NPG*NPG; i+=256){
        int r = i>>6, c = i&63;
        sL[i] = (sC[i] > 0.f) ? lrelu(sf1[c] + sf2[r]) : -1e30f;
    }
    __syncthreads();
    if (t < NPG){
        float m = -1e30f;
        for (int r=0; r<NPG; r++) m = fmaxf(m, sL[r*NPG+t]);
        float den = 0.f;
        for (int r=0; r<NPG; r++){
            float cc = sC[r*NPG+t];
            if (cc > 0.f) den += cc*expf(sL[r*NPG+t]-m);
        }
        sm_[t] = m; sden[t] = den;
    }
    __syncthreads();
    for (int i=t; i<NPG*NPG; i+=256){
        int c = i & 63;
        float cc = sC[i];
        float s = (cc > 0.f) ? cc*expf(sL[i]-sm_[c])/sden[c] : 0.f;
        sL[i] = s;
        g_S[b*NPG*NPG+i] = s;
    }
    __syncthreads();
    const float4* X4 = (const float4*)x;
    int tx = t & 31, ty = t >> 5;
    for (int cc=0; cc<8; cc++){
        int c = ty*8+cc;
        float4 acc = make_float4(0.f,0.f,0.f,0.f);
        for (int r=0; r<NPG; r++){
            float s = sL[r*NPG+c];
            float4 v = X4[(b*NPG+r)*HD4 + tx];
            acc.x += s*v.x; acc.y += s*v.y; acc.z += s*v.z; acc.w += s*v.w;
        }
        uint32_t pxy0,pxy1,pxy2, pzw0,pzw1,pzw2;
        split2pack(acc.x, acc.y, pxy0, pxy1, pxy2);
        split2pack(acc.z, acc.w, pzw0, pzw1, pzw2);
        size_t base = (size_t)(b*64+c)*128 + tx*4;
        *(uint32_t*)(g_aggP + base)                    = pxy0;
        *(uint32_t*)(g_aggP + base + 2)                = pzw0;
        *(uint32_t*)(g_aggP + NNODES*HD + base)        = pxy1;
        *(uint32_t*)(g_aggP + NNODES*HD + base + 2)    = pzw1;
        *(uint32_t*)(g_aggP + 2*NNODES*HD + base)      = pxy2;
        *(uint32_t*)(g_aggP + 2*NNODES*HD + base + 2)  = pzw2;
    }
}

// ---------------- xc compute + split + first hop (merged) ----------------
__global__ void k_xc_hop(const float* __restrict__ x, float4* __restrict__ vout){
    extern __shared__ float sh[];
    float* sxc = sh;            // 8192 floats
    float* sAm = sh + 8192;     // 4096 floats
    int b = blockIdx.x, t = threadIdx.x;
    for (int i=t; i<4096; i+=256) sAm[i] = g_A[b*4096+i];
    for (int i=t; i<4096; i+=256){
        int idx2 = i*2;
        size_t gi = (size_t)b*8192 + idx2;
        float x0 = x[gi], x1 = x[gi+1];
        float p00 = g_P[gi], p01 = g_P[gi+1];
        float p10 = g_P[NNODES*HD + gi], p11 = g_P[NNODES*HD + gi+1];
        float v0 = 0.5f*(lrelu(x0+p00) + lrelu(x0+p10));
        float v1 = 0.5f*(lrelu(x1+p01) + lrelu(x1+p11));
        sxc[idx2] = v0; sxc[idx2+1] = v1;
        uint32_t q0,q1,q2;
        split2pack(v0, v1, q0, q1, q2);
        *(uint32_t*)(g_xcP + gi)                = q0;
        *(uint32_t*)(g_xcP + NNODES*HD + gi)    = q1;
        *(uint32_t*)(g_xcP + 2*NNODES*HD + gi)  = q2;
    }
    __syncthreads();
    int tx = t & 31, ty = t >> 5;
    const float4* sx4 = (const float4*)sxc;
    for (int cc=0; cc<8; cc++){
        int c = ty*8+cc;
        float4 acc = make_float4(0.f,0.f,0.f,0.f);
        for (int r=0; r<NPG; r++){
            float a = sAm[r*NPG+c];
            float4 v = sx4[r*32 + tx];
            acc.x += a*v.x; acc.y += a*v.y; acc.z += a*v.z; acc.w += a*v.w;
        }
        vout[(b*NPG+c)*HD4 + tx] = acc;
    }
}

// ---------------- cluster score softmax + top-k + outputs (merged; full-scope barriers) ----------------
__global__ void k_topk_score(const float* __restrict__ x, float* __restrict__ out){
    __shared__ float s[64];
    __shared__ float red[64];
    __shared__ int lp[KK];
    int b = blockIdx.x, t = threadIdx.x;
    // softmax of (f1+f2) over the 64 nodes of batch b
    if (t < 64){ float v = g_f[b*64+t] + g_f[NNODES + b*64+t]; s[t] = v; red[t] = v; }
    __syncthreads();
    for (int o=32; o>0; o>>=1){ if (t<o) red[t] = fmaxf(red[t], red[t+o]); __syncthreads(); }
    float m = red[0];
    __syncthreads();
    if (t < 64){ float e = expf(s[t] - m); s[t] = e; red[t] = e; }
    __syncthreads();
    for (int o=32; o>0; o>>=1){ if (t<o) red[t] += red[t+o]; __syncthreads(); }
    float den = red[0];
    __syncthreads();
    if (t < 64) s[t] = s[t] / den;
    __syncthreads();
    // stable descending top-k
    if (t < 64){
        float v = s[t];
        int rank = 0;
        for (int j=0; j<64; j++){
            float u = s[j];
            rank += (u > v) || (u == v && j < t);
        }
        if (rank < KK){
            lp[rank] = t;
            g_perm[b*KK+rank] = b*64+t;
            out[OFF_B + b*KK+rank] = (float)b;
            out[OFF_P + b*KK+rank] = (float)(b*64+t);
        }
    }
    __syncthreads();
    const float4* x4 = (const float4*)x;
    float4* o4 = (float4*)out;
    for (int i=t; i<KK*32; i+=256){
        int r = i >> 5, f = i & 31;
        int p = lp[r];
        float sc = s[p];
        float4 v = x4[(b*64+p)*32 + f];
        o4[(size_t)(b*KK+r)*32 + f] = make_float4(v.x*sc, v.y*sc, v.z*sc, v.w*sc);
    }
}

// ---------------- A2 block triple-product ----------------
__global__ void k_A2(float* __restrict__ out){
    int b = blockIdx.x, t = threadIdx.x;
    __shared__ float sA[NPG*NPG];
    __shared__ float sS[NPG*NPG];
    __shared__ float sU[NPG*KK];
    __shared__ int   sI[KK];
    for (int i=t; i<NPG*NPG; i+=256){ sA[i] = g_A[b*NPG*NPG+i]; sS[i] = g_S[b*NPG*NPG+i]; }
    if (t < KK) sI[t] = g_perm[b*KK+t] - b*NPG;
    __syncthreads();
    for (int idx=t; idx<NPG*KK; idx+=256){
        int r = idx / KK, j = idx - r*KK;
        int pj = sI[j];
        float acc = 0.f;
        for (int c=0; c<NPG; c++) acc += sA[r*NPG+c]*sS[c*NPG+pj];
        sU[idx] = acc;
    }
    __syncthreads();
    for (int idx=t; idx<KK*KK; idx+=256){
        int i2 = idx / KK, j = idx - i2*KK;
        int pi = sI[i2];
        float acc = 0.f;
        for (int r=0; r<NPG; r++) acc += sS[r*NPG+pi]*sU[r*KK+j];
        float v = (i2 == j) ? 1.0f : acc;
        out[(size_t)OFF_A2 + (size_t)(b*KK+i2)*NK + (b*KK+j)] = v;
    }
}

// ---------------- host ----------------
static void launch_attention(int base,
                             const __nv_bfloat16* kvP,
                             const float* q0, const float* q1,
                             const float* W3,
                             __nv_bfloat16* wkP, __nv_bfloat16* w1P, __nv_bfloat16* w2P,
                             __nv_bfloat16* h0P, __nv_bfloat16* h1P, float* h2)
{
    // a = kv @ Wk -> h0 planes (concat fused into epilogue)
    k_pgemm<3><<<dim3(1,32,2),256,GSMEM>>>(
        kvP, 0LL, (long long)NNODES*HD,
        wkP + (size_t)base*128*128, 128LL*128, 4LL*128*128,
        128, 128,
        nullptr, 0LL,
        h0P, (long long)NNODES*512, 2LL*NNODES*512,
        q0, q1);
    // h1 planes = split(lrelu(h0 @ W1))
    k_pgemm<2><<<dim3(2,32,2),256,GSMEM>>>(
        h0P, (long long)NNODES*512, 2LL*NNODES*512,
        w1P + (size_t)base*256*512, 256LL*512, 4LL*256*512,
        512, 256,
        nullptr, 0LL,
        h1P, (long long)NNODES*256, 2LL*NNODES*256,
        nullptr, nullptr);
    // h2 = lrelu(h1 @ W2)  (fp32)
    k_pgemm<1><<<dim3(1,32,2),256,GSMEM>>>(
        h1P, (long long)NNODES*256, 2LL*NNODES*256,
        w2P + (size_t)base*128*256, 128LL*256, 4LL*128*256,
        256, 128,
        h2, (long long)NNODES*HD,
        nullptr, 0LL, 0LL,
        nullptr, nullptr);
    // logits + per-batch softmax
    k_w3s<<<2*NBATCH,256>>>(W3, base);
}

extern "C" void kernel_launch(void* const* d_in, const int* in_sizes, int n_in,
                              void* d_out, int out_size)
{
    (void)in_sizes; (void)n_in; (void)out_size;
    const float* x    = (const float*)d_in[0];
    const int*   ei   = (const int*)  d_in[1];
    const float* ew   = (const float*)d_in[2];
    const float* txg  = (const float*)d_in[3];
    const float* Wk   = (const float*)d_in[5];
    const float* W1   = (const float*)d_in[6];
    const float* W2   = (const float*)d_in[7];
    const float* W3   = (const float*)d_in[8];
    const float* linW = (const float*)d_in[9];
    float* out = (float*)d_out;
    const int* row = ei;
    const int* col = ei + NE;

    cudaFuncSetAttribute(k_pgemm<0>, cudaFuncAttributeMaxDynamicSharedMemorySize, GSMEM);
    cudaFuncSetAttribute(k_pgemm<1>, cudaFuncAttributeMaxDynamicSharedMemorySize, GSMEM);
    cudaFuncSetAttribute(k_pgemm<2>, cudaFuncAttributeMaxDynamicSharedMemorySize, GSMEM);
    cudaFuncSetAttribute(k_pgemm<3>, cudaFuncAttributeMaxDynamicSharedMemorySize, GSMEM);
    cudaFuncSetAttribute(k_xc_hop, cudaFuncAttributeMaxDynamicSharedMemorySize, 49152);

    float *p_tmp,*p_xq,*p_qt,*p_h2,*p_P;
    __nv_bfloat16 *p_XP,*p_xcP,*p_aggP,*p_WkP,*p_W1P,*p_W2P,*p_LWP,*p_h0P,*p_h1P;
    cudaGetSymbolAddress((void**)&p_tmp,  g_tmp);
    cudaGetSymbolAddress((void**)&p_xq,   g_xq);
    cudaGetSymbolAddress((void**)&p_qt,   g_qt);
    cudaGetSymbolAddress((void**)&p_h2,   g_h2);
    cudaGetSymbolAddress((void**)&p_P,    g_P);
    cudaGetSymbolAddress((void**)&p_XP,   g_XP);
    cudaGetSymbolAddress((void**)&p_xcP,  g_xcP);
    cudaGetSymbolAddress((void**)&p_aggP, g_aggP);
    cudaGetSymbolAddress((void**)&p_WkP,  g_WkP);
    cudaGetSymbolAddress((void**)&p_W1P,  g_W1P);
    cudaGetSymbolAddress((void**)&p_W2P,  g_W2P);
    cudaGetSymbolAddress((void**)&p_LWP,  g_LWP);
    cudaGetSymbolAddress((void**)&p_h0P,  g_h0P);
    cudaGetSymbolAddress((void**)&p_h1P,  g_h1P);

    // prep: weight splits (+transpose), x split, qt gather
    k_prep<<<(PREP_QT+255)/256,256>>>(Wk, W1, W2, linW, x, txg);

    // graph setup
    k_init<<<1024,256>>>();
    k_deg<<<NE/256,256>>>(col, ew);
    k_dinv<<<NNODES/256,256>>>();
    k_build<<<(NE+NNODES)/256,256>>>(row, col, ew);

    // x_q = hop(hop(x))
    k_hop<<<NBATCH,256>>>((const float4*)x, (float4*)p_tmp);
    k_hop<<<NBATCH,256>>>((const float4*)p_tmp, (float4*)p_xq);

    // f1 = att(x, x_q); f2 = att(x, qt)
    launch_attention(0, p_XP, p_xq, p_qt, W3, p_WkP, p_W1P, p_W2P, p_h0P, p_h1P, p_h2);

    // edge softmax -> S, agg planes
    k_edge<<<NBATCH,256>>>(x);

    // P[h] = agg @ lin_W[h]  (fp32 out)
    k_pgemm<0><<<dim3(1,32,2),256,GSMEM>>>(
        p_aggP, 0LL, (long long)NNODES*HD,
        p_LWP, 128LL*128, 2LL*128*128,
        128, 128,
        p_P, (long long)NNODES*HD,
        nullptr, 0LL, 0LL,
        nullptr, nullptr);

    // xc = mean lrelu(x + P[h]); split; first hop
    k_xc_hop<<<NBATCH,256,49152>>>(x, (float4*)p_tmp);
    k_hop<<<NBATCH,256>>>((const float4*)p_tmp, (float4*)p_xq);

    // g1 = att(xc, x_q2); g2 = att(xc, qt)
    launch_attention(2, p_xcP, p_xq, p_qt, W3, p_WkP, p_W1P, p_W2P, p_h0P, p_h1P, p_h2);

    // score softmax + top-k + x_out/batch/perm
    k_topk_score<<<NBATCH,256>>>(x, out);

    cudaMemsetAsync(out + OFF_A2, 0, (size_t)NK*NK*sizeof(float));
    k_A2<<<NBATCH,256>>>(out);
}

// round 7
// speedup vs baseline: 1.4075x; 1.0783x over previous
#include <cuda_runtime.h>
#include <cuda_bf16.h>
#include <cstdint>

// ---------------- problem constants ----------------
#define NNODES 4096
#define NBATCH 64
#define NPG    64
#define HD     128
#define HD4    32
#define NE     131072
#define EPB    2048          // edges per batch
#define KK     52
#define NK     3328

#define LEN_X  (NK*HD)
#define OFF_A2 (LEN_X)
#define OFF_B  (OFF_A2 + NK*NK)
#define OFF_P  (OFF_B + NK)

// GEMM smem: 3 planes x 128 rows x 20 u32 (40 halfs, 32 used) per side
#define ROWU 20
#define PLU  (128*ROWU)
#define GSMEM (6*PLU*4)          // 61440 bytes

// ---------------- scratch ----------------
__device__ float g_A[NBATCH*NPG*NPG];
__device__ float g_Cnt[NBATCH*NPG*NPG];
__device__ float g_S[NBATCH*NPG*NPG];
__device__ float g_xq[NNODES*HD];
__device__ float g_qt[NNODES*HD];
__device__ float g_f[2*NNODES];
__device__ float g_P[2*NNODES*HD];
__device__ int   g_perm[NK];

// bf16 split planes (plane-major), 16B-aligned
__device__ __align__(16) __nv_bfloat16 g_XP  [3*NNODES*HD];
__device__ __align__(16) __nv_bfloat16 g_xcP [3*NNODES*HD];
__device__ __align__(16) __nv_bfloat16 g_aggP[3*NNODES*HD];
__device__ __align__(16) __nv_bfloat16 g_WkP [3*4*128*128];
__device__ __align__(16) __nv_bfloat16 g_W1P [3*4*256*512];
__device__ __align__(16) __nv_bfloat16 g_W2P [3*4*128*256];
__device__ __align__(16) __nv_bfloat16 g_LWP [3*2*128*128];
__device__ __align__(16) __nv_bfloat16 g_h0P [3*2*NNODES*512];
__device__ __align__(16) __nv_bfloat16 g_h1P [3*2*NNODES*256];

__device__ __forceinline__ float lrelu(float v){ return v > 0.f ? v : 0.01f*v; }

__device__ __forceinline__ void split3(float a, unsigned short& h0, unsigned short& h1, unsigned short& h2){
    __nv_bfloat16 b0 = __float2bfloat16(a); float r1 = a - __bfloat162float(b0);
    __nv_bfloat16 b1 = __float2bfloat16(r1); float r2 = r1 - __bfloat162float(b1);
    __nv_bfloat16 b2 = __float2bfloat16(r2);
    h0 = __bfloat16_as_ushort(b0);
    h1 = __bfloat16_as_ushort(b1);
    h2 = __bfloat16_as_ushort(b2);
}
__device__ __forceinline__ void split2pack(float a, float b, uint32_t& p0, uint32_t& p1, uint32_t& p2){
    unsigned short a0,a1,a2,b0,b1,b2;
    split3(a, a0, a1, a2);
    split3(b, b0, b1, b2);
    p0 = (uint32_t)a0 | ((uint32_t)b0 << 16);
    p1 = (uint32_t)a1 | ((uint32_t)b1 << 16);
    p2 = (uint32_t)a2 | ((uint32_t)b2 << 16);
}

__device__ __forceinline__ void mma16816(float* d, const uint32_t* a, const uint32_t* b){
    asm volatile(
        "mma.sync.aligned.m16n8k16.row.col.f32.bf16.bf16.f32 "
        "{%0,%1,%2,%3}, {%4,%5,%6,%7}, {%8,%9}, {%0,%1,%2,%3};"
        : "+f"(d[0]), "+f"(d[1]), "+f"(d[2]), "+f"(d[3])
        : "r"(a[0]), "r"(a[1]), "r"(a[2]), "r"(a[3]), "r"(b[0]), "r"(b[1]));
}

// ---------------- fill + mma macro-body (shared by pgemm and w2s) ----------------
#define GEMM_MAINLOOP(AP, aZ, aP, BP, bZ, bP, KTOT)                                        \
    int chunks = (KTOT) >> 5;                                                              \
    int fr = t >> 1, fkh = t & 1;                                                          \
    for (int c = 0; c < chunks; c++){                                                      \
        int k0 = c << 5;                                                                   \
        _Pragma("unroll")                                                                  \
        for (int p=0; p<3; p++){                                                           \
            const __nv_bfloat16* as = (AP) + (size_t)p*(aP) + (size_t)z*(aZ) + (size_t)(rowBase+fr)*(KTOT) + k0 + fkh*16; \
            uint4 v0 = *(const uint4*)as;                                                  \
            uint4 v1 = *(const uint4*)(as+8);                                              \
            uint32_t* d = smu + p*PLU + fr*ROWU + fkh*8;                                   \
            d[0]=v0.x; d[1]=v0.y; d[2]=v0.z; d[3]=v0.w;                                    \
            d[4]=v1.x; d[5]=v1.y; d[6]=v1.z; d[7]=v1.w;                                    \
            const __nv_bfloat16* bs = (BP) + (size_t)p*(bP) + (size_t)z*(bZ) + (size_t)(colBase+fr)*(KTOT) + k0 + fkh*16; \
            uint4 w0 = *(const uint4*)bs;                                                  \
            uint4 w1 = *(const uint4*)(bs+8);                                              \
            uint32_t* db = smu + (3+p)*PLU + fr*ROWU + fkh*8;                              \
            db[0]=w0.x; db[1]=w0.y; db[2]=w0.z; db[3]=w0.w;                                \
            db[4]=w1.x; db[5]=w1.y; db[6]=w1.z; db[7]=w1.w;                                \
        }                                                                                  \
        __syncthreads();                                                                   \
        _Pragma("unroll")                                                                  \
        for (int s=0; s<2; s++){                                                           \
            uint32_t bf[3][4][2];                                                          \
            _Pragma("unroll")                                                              \
            for (int ni=0; ni<4; ni++){                                                    \
                int bbase = (warpN + ni*8 + (lane>>2))*ROWU + s*8 + (lane&3);              \
                bf[0][ni][0]=smu[3*PLU+bbase]; bf[0][ni][1]=smu[3*PLU+bbase+4];            \
                bf[1][ni][0]=smu[4*PLU+bbase]; bf[1][ni][1]=smu[4*PLU+bbase+4];            \
                bf[2][ni][0]=smu[5*PLU+bbase]; bf[2][ni][1]=smu[5*PLU+bbase+4];            \
            }                                                                              \
            _Pragma("unroll")                                                              \
            for (int apl=0; apl<3; apl++){                                                 \
                const uint32_t* As = smu + apl*PLU;                                        \
                uint32_t af[4][4];                                                         \
                _Pragma("unroll")                                                          \
                for (int mi=0; mi<4; mi++){                                                \
                    int abase = (warpM + mi*16 + (lane>>2))*ROWU + s*8 + (lane&3);         \
                    af[mi][0]=As[abase];                                                   \
                    af[mi][1]=As[abase+8*ROWU];                                            \
                    af[mi][2]=As[abase+4];                                                 \
                    af[mi][3]=As[abase+8*ROWU+4];                                          \
                }                                                                          \
                int nb = (apl==0)?3:((apl==1)?2:1);                                        \
                _Pragma("unroll")                                                          \
                for (int bpl=0; bpl<3; bpl++){                                             \
                    if (bpl >= nb) break;                                                  \
                    _Pragma("unroll")                                                      \
                    for (int mi=0; mi<4; mi++)                                             \
                        _Pragma("unroll")                                                  \
                        for (int ni=0; ni<4; ni++)                                         \
                            mma16816(acc[mi*4+ni], af[mi], bf[bpl][ni]);                   \
                }                                                                          \
            }                                                                              \
        }                                                                                  \
        __syncthreads();                                                                   \
    }

// ---------------- pre-split GEMM (EPI 0=fp32, 2=lrelu+split planes, 3=h0 concat) ----------------
template<int EPI>
__global__ void __launch_bounds__(256) k_pgemm(
    const __nv_bfloat16* __restrict__ AP, long long aZ, long long aP,
    const __nv_bfloat16* __restrict__ BP, long long bZ, long long bP,
    int Ktot, int Nc,
    float* __restrict__ Cout, long long cZ,
    __nv_bfloat16* __restrict__ OP, long long oZ, long long oP,
    const float* __restrict__ q0, const float* __restrict__ q1)
{
    extern __shared__ uint32_t smu[];
    int t = threadIdx.x, wid = t >> 5, lane = t & 31;
    int z = blockIdx.z;
    int rowBase = blockIdx.y * 128;
    int colBase = blockIdx.x * 128;
    int warpM = (wid >> 2) * 64;
    int warpN = (wid & 3) * 32;

    float acc[16][4];
#pragma unroll
    for (int i=0;i<16;i++){ acc[i][0]=0.f; acc[i][1]=0.f; acc[i][2]=0.f; acc[i][3]=0.f; }

    GEMM_MAINLOOP(AP, aZ, aP, BP, bZ, bP, Ktot)

#pragma unroll
    for (int mi=0; mi<4; mi++){
#pragma unroll
        for (int ni=0; ni<4; ni++){
            float* d = acc[mi*4+ni];
            int r0 = rowBase + warpM + mi*16 + (lane>>2);
            int c0 = colBase + warpN + ni*8 + (lane&3)*2;
            if (EPI == 0){
                float* cp = Cout + (size_t)z*cZ;
                *(float2*)(cp + (size_t)r0*Nc + c0)     = make_float2(d[0], d[1]);
                *(float2*)(cp + (size_t)(r0+8)*Nc + c0) = make_float2(d[2], d[3]);
            } else if (EPI == 2){
#pragma unroll
                for (int qi=0; qi<2; qi++){
                    int row = r0 + qi*8;
                    float da = lrelu(d[qi*2]), db = lrelu(d[qi*2+1]);
                    uint32_t p0,p1,p2;
                    split2pack(da, db, p0, p1, p2);
                    size_t off = (size_t)z*oZ + (size_t)row*Nc + c0;
                    *(uint32_t*)(OP + off)        = p0;
                    *(uint32_t*)(OP + oP + off)   = p1;
                    *(uint32_t*)(OP + 2*oP + off) = p2;
                }
            } else {   // EPI == 3: h0 concat
                const float* q = z ? q1 : q0;
#pragma unroll
                for (int qi=0; qi<2; qi++){
                    int row = r0 + qi*8;
                    float av = d[qi*2], bv = d[qi*2+1];
                    float qa = q[(size_t)row*128 + c0];
                    float qb = q[(size_t)row*128 + c0 + 1];
                    float sa[4] = {av, qa, av-qa, av*qa};
                    float sb[4] = {bv, qb, bv-qb, bv*qb};
#pragma unroll
                    for (int sec=0; sec<4; sec++){
                        uint32_t p0,p1,p2;
                        split2pack(sa[sec], sb[sec], p0, p1, p2);
                        size_t off = (size_t)z*oZ + (size_t)row*512 + sec*128 + c0;
                        *(uint32_t*)(OP + off)        = p0;
                        *(uint32_t*)(OP + oP + off)   = p1;
                        *(uint32_t*)(OP + 2*oP + off) = p2;
                    }
                }
            }
        }
    }
}

// ---------------- W2 GEMM + W3 dot + per-batch softmax (merged) ----------------
__global__ void __launch_bounds__(256) k_w2s(const float* __restrict__ W3, int base)
{
    extern __shared__ uint32_t smu[];
    __shared__ float sw3[128];
    __shared__ float slog[4][128];
    __shared__ float sl[128];
    __shared__ float sred[128];
    int t = threadIdx.x, wid = t >> 5, lane = t & 31;
    int z = blockIdx.z;
    int rowBase = blockIdx.y * 128;
    int colBase = 0;
    int warpM = (wid >> 2) * 64;
    int warpN = (wid & 3) * 32;

    if (t < 128) sw3[t] = W3[(size_t)(base+z)*128 + t];

    float acc[16][4];
#pragma unroll
    for (int i=0;i<16;i++){ acc[i][0]=0.f; acc[i][1]=0.f; acc[i][2]=0.f; acc[i][3]=0.f; }

    GEMM_MAINLOOP(g_h1P, (long long)NNODES*256, 2LL*NNODES*256,
                  g_W2P + (size_t)base*128*256, 128LL*256, 4LL*128*256, 256)

    // per-row dot with w3 (h2 = lrelu(gemm) first)
#pragma unroll
    for (int mi=0; mi<4; mi++){
        float pr0 = 0.f, pr1 = 0.f;
#pragma unroll
        for (int ni=0; ni<4; ni++){
            float* d = acc[mi*4+ni];
            int c0 = warpN + ni*8 + (lane&3)*2;
            pr0 += sw3[c0]*lrelu(d[0]) + sw3[c0+1]*lrelu(d[1]);
            pr1 += sw3[c0]*lrelu(d[2]) + sw3[c0+1]*lrelu(d[3]);
        }
        pr0 += __shfl_xor_sync(0xffffffffu, pr0, 1);
        pr0 += __shfl_xor_sync(0xffffffffu, pr0, 2);
        pr1 += __shfl_xor_sync(0xffffffffu, pr1, 1);
        pr1 += __shfl_xor_sync(0xffffffffu, pr1, 2);
        if ((lane & 3) == 0){
            int rl = warpM + mi*16 + (lane>>2);
            slog[wid & 3][rl]     = pr0;
            slog[wid & 3][rl + 8] = pr1;
        }
    }
    __syncthreads();
    if (t < 128){
        float v = slog[0][t] + slog[1][t] + slog[2][t] + slog[3][t];
        v = lrelu(v);
        sl[t] = v; sred[t] = v;
    }
    __syncthreads();
    // two softmax groups of 64 (full-scope barriers)
    for (int o=32; o>0; o>>=1){ if (t<128 && (t&63)<o) sred[t] = fmaxf(sred[t], sred[t+o]); __syncthreads(); }
    float m = (t < 128) ? sred[t & 64] : 0.f;
    __syncthreads();
    if (t < 128){ float e = expf(sl[t] - m); sl[t] = e; sred[t] = e; }
    __syncthreads();
    for (int o=32; o>0; o>>=1){ if (t<128 && (t&63)<o) sred[t] += sred[t+o]; __syncthreads(); }
    if (t < 128) g_f[(size_t)z*NNODES + rowBase + t] = sl[t] / sred[t & 64];
}

// ---------------- prep: split weights (+transpose), split x, build qt ----------------
#define PREP_WK   65536
#define PREP_W1   (PREP_WK + 524288)
#define PREP_W2   (PREP_W1 + 131072)
#define PREP_LW   (PREP_W2 + 32768)
#define PREP_X    (PREP_LW + 524288)
#define PREP_QT   (PREP_X + 524288)

__global__ void k_prep(const float* __restrict__ Wk, const float* __restrict__ W1,
                       const float* __restrict__ W2, const float* __restrict__ LW,
                       const float* __restrict__ x, const float* __restrict__ txg)
{
    int i = blockIdx.x*blockDim.x + threadIdx.x;
    if (i >= PREP_QT) return;
    unsigned short h0,h1,h2;
    if (i < PREP_WK){
        int z = i >> 14, rem = i & 16383, k = rem >> 7, n = rem & 127;
        split3(Wk[i], h0, h1, h2);
        size_t d = (size_t)(z*128 + n)*128 + k;
        g_WkP[d] = __ushort_as_bfloat16(h0);
        g_WkP[4*16384 + d] = __ushort_as_bfloat16(h1);
        g_WkP[8*16384 + d] = __ushort_as_bfloat16(h2);
    } else if (i < PREP_W1){
        int j = i - PREP_WK;
        int z = j >> 17, rem = j & 131071, k = rem >> 8, n = rem & 255;
        split3(W1[j], h0, h1, h2);
        size_t d = (size_t)(z*256 + n)*512 + k;
        g_W1P[d] = __ushort_as_bfloat16(h0);
        g_W1P[4*131072 + d] = __ushort_as_bfloat16(h1);
        g_W1P[(size_t)8*131072 + d] = __ushort_as_bfloat16(h2);
    } else if (i < PREP_W2){
        int j = i - PREP_W1;
        int z = j >> 15, rem = j & 32767, k = rem >> 7, n = rem & 127;
        split3(W2[j], h0, h1, h2);
        size_t d = (size_t)(z*128 + n)*256 + k;
        g_W2P[d] = __ushort_as_bfloat16(h0);
        g_W2P[4*32768 + d] = __ushort_as_bfloat16(h1);
        g_W2P[8*32768 + d] = __ushort_as_bfloat16(h2);
    } else if (i < PREP_LW){
        int j = i - PREP_W2;
        int z = j >> 14, rem = j & 16383, k = rem >> 7, n = rem & 127;
        split3(LW[j], h0, h1, h2);
        size_t d = (size_t)(z*128 + n)*128 + k;
        g_LWP[d] = __ushort_as_bfloat16(h0);
        g_LWP[2*16384 + d] = __ushort_as_bfloat16(h1);
        g_LWP[4*16384 + d] = __ushort_as_bfloat16(h2);
    } else if (i < PREP_X){
        int j = i - PREP_LW;
        split3(x[j], h0, h1, h2);
        g_XP[j] = __ushort_as_bfloat16(h0);
        g_XP[NNODES*HD + j] = __ushort_as_bfloat16(h1);
        g_XP[2*NNODES*HD + j] = __ushort_as_bfloat16(h2);
    } else {
        int j = i - PREP_X;
        g_qt[j] = txg[((j >> 13) << 7) | (j & 127)];
    }
}

// ---------------- graph build + 2 hops, all per-batch in smem ----------------
// smem: sA 4096 | sCnt 4096 | sx 8192 | stmp 8192 floats = 96 KB
__global__ void k_graph(const int* __restrict__ row, const int* __restrict__ col,
                        const float* __restrict__ ew, const float* __restrict__ x,
                        float4* __restrict__ xqout)
{
    extern __shared__ float sh[];
    float* sA   = sh;
    float* sCnt = sh + 4096;
    float* sx   = sh + 8192;
    float* stmp = sh + 16384;
    __shared__ float sdeg[64];
    int b = blockIdx.x, t = threadIdx.x;
    for (int i=t; i<4096; i+=256){ sA[i]=0.f; sCnt[i]=0.f; }
    if (t < 64) sdeg[t] = 1.0f;
    __syncthreads();
    const int* er = row + b*EPB;
    const int* ec = col + b*EPB;
    const float* w = ew + b*EPB;
    for (int i=t; i<EPB; i+=256) atomicAdd(&sdeg[ec[i]&63], w[i]);
    __syncthreads();
    if (t < 64) sdeg[t] = rsqrtf(sdeg[t]);
    __syncthreads();
    for (int i=t; i<EPB; i+=256){
        int r = er[i]&63, c = ec[i]&63;
        atomicAdd(&sA[r*64+c], sdeg[r]*w[i]*sdeg[c]);
        atomicAdd(&sCnt[r*64+c], 1.0f);
    }
    if (t < 64){
        atomicAdd(&sA[t*65], sdeg[t]*sdeg[t]);
        atomicAdd(&sCnt[t*65], 1.0f);
    }
    __syncthreads();
    for (int i=t; i<4096; i+=256){ g_A[b*4096+i] = sA[i]; g_Cnt[b*4096+i] = sCnt[i]; }
    // load x block
    float4* sx4 = (float4*)sx;
    const float4* gx4 = (const float4*)(x + (size_t)b*8192);
    for (int i=t; i<2048; i+=256) sx4[i] = gx4[i];
    __syncthreads();
    int tx = t & 31, ty = t >> 5;
    float4* st4 = (float4*)stmp;
    for (int cc=0; cc<8; cc++){
        int c = ty*8+cc;
        float4 acc = make_float4(0.f,0.f,0.f,0.f);
        for (int r=0; r<64; r++){
            float a = sA[r*64+c];
            float4 v = sx4[r*32+tx];
            acc.x += a*v.x; acc.y += a*v.y; acc.z += a*v.z; acc.w += a*v.w;
        }
        st4[c*32+tx] = acc;
    }
    __syncthreads();
    for (int cc=0; cc<8; cc++){
        int c = ty*8+cc;
        float4 acc = make_float4(0.f,0.f,0.f,0.f);
        for (int r=0; r<64; r++){
            float a = sA[r*64+c];
            float4 v = st4[r*32+tx];
            acc.x += a*v.x; acc.y += a*v.y; acc.z += a*v.z; acc.w += a*v.w;
        }
        xqout[(b*64+c)*32 + tx] = acc;
    }
}

// ---------------- edge softmax + S + agg planes ----------------
__global__ void k_edge(const float* __restrict__ x){
    int b = blockIdx.x, t = threadIdx.x;
    __shared__ float sC[NPG*NPG];
    __shared__ float sL[NPG*NPG];
    __shared__ float sf1[NPG], sf2[NPG], sm_[NPG], sden[NPG];
    for (int i=t; i<NPG*NPG; i+=256) sC[i] = g_Cnt[b*NPG*NPG+i];
    if (t < NPG){ sf1[t] = g_f[b*NPG+t]; sf2[t] = g_f[NNODES + b*NPG+t]; }
    __syncthreads();
    for (int i=t; i<NPG*NPG; i+=256){
        int r = i>>6, c = i&63;
        sL[i] = (sC[i] > 0.f) ? lrelu(sf1[c] + sf2[r]) : -1e30f;
    }
    __syncthreads();
    if (t < NPG){
        float m = -1e30f;
        for (int r=0; r<NPG; r++) m = fmaxf(m, sL[r*NPG+t]);
        float den = 0.f;
        for (int r=0; r<NPG; r++){
            float cc = sC[r*NPG+t];
            if (cc > 0.f) den += cc*expf(sL[r*NPG+t]-m);
        }
        sm_[t] = m; sden[t] = den;
    }
    __syncthreads();
    for (int i=t; i<NPG*NPG; i+=256){
        int c = i & 63;
        float cc = sC[i];
        float s = (cc > 0.f) ? cc*expf(sL[i]-sm_[c])/sden[c] : 0.f;
        sL[i] = s;
        g_S[b*NPG*NPG+i] = s;
    }
    __syncthreads();
    const float4* X4 = (const float4*)x;
    int tx = t & 31, ty = t >> 5;
    for (int cc=0; cc<8; cc++){
        int c = ty*8+cc;
        float4 acc = make_float4(0.f,0.f,0.f,0.f);
        for (int r=0; r<NPG; r++){
            float s = sL[r*NPG+c];
            float4 v = X4[(b*NPG+r)*HD4 + tx];
            acc.x += s*v.x; acc.y += s*v.y; acc.z += s*v.z; acc.w += s*v.w;
        }
        uint32_t pxy0,pxy1,pxy2, pzw0,pzw1,pzw2;
        split2pack(acc.x, acc.y, pxy0, pxy1, pxy2);
        split2pack(acc.z, acc.w, pzw0, pzw1, pzw2);
        size_t base = (size_t)(b*64+c)*128 + tx*4;
        *(uint32_t*)(g_aggP + base)                    = pxy0;
        *(uint32_t*)(g_aggP + base + 2)                = pzw0;
        *(uint32_t*)(g_aggP + NNODES*HD + base)        = pxy1;
        *(uint32_t*)(g_aggP + NNODES*HD + base + 2)    = pzw1;
        *(uint32_t*)(g_aggP + 2*NNODES*HD + base)      = pxy2;
        *(uint32_t*)(g_aggP + 2*NNODES*HD + base + 2)  = pzw2;
    }
}

// ---------------- xc compute + split + hop + hop (merged) ----------------
// smem: sxc 8192 | sA 4096 | stmp 8192 floats = 80 KB
__global__ void k_xc_hop2(const float* __restrict__ x, float4* __restrict__ xqout){
    extern __shared__ float sh[];
    float* sxc  = sh;
    float* sAm  = sh + 8192;
    float* stmp = sh + 12288;
    int b = blockIdx.x, t = threadIdx.x;
    for (int i=t; i<4096; i+=256) sAm[i] = g_A[b*4096+i];
    for (int i=t; i<4096; i+=256){
        int idx2 = i*2;
        size_t gi = (size_t)b*8192 + idx2;
        float x0 = x[gi], x1 = x[gi+1];
        float p00 = g_P[gi], p01 = g_P[gi+1];
        float p10 = g_P[NNODES*HD + gi], p11 = g_P[NNODES*HD + gi+1];
        float v0 = 0.5f*(lrelu(x0+p00) + lrelu(x0+p10));
        float v1 = 0.5f*(lrelu(x1+p01) + lrelu(x1+p11));
        sxc[idx2] = v0; sxc[idx2+1] = v1;
        uint32_t q0,q1,q2;
        split2pack(v0, v1, q0, q1, q2);
        *(uint32_t*)(g_xcP + gi)                = q0;
        *(uint32_t*)(g_xcP + NNODES*HD + gi)    = q1;
        *(uint32_t*)(g_xcP + 2*NNODES*HD + gi)  = q2;
    }
    __syncthreads();
    int tx = t & 31, ty = t >> 5;
    const float4* sx4 = (const float4*)sxc;
    float4* st4 = (float4*)stmp;
    for (int cc=0; cc<8; cc++){
        int c = ty*8+cc;
        float4 acc = make_float4(0.f,0.f,0.f,0.f);
        for (int r=0; r<NPG; r++){
            float a = sAm[r*NPG+c];
            float4 v = sx4[r*32 + tx];
            acc.x += a*v.x; acc.y += a*v.y; acc.z += a*v.z; acc.w += a*v.w;
        }
        st4[c*32+tx] = acc;
    }
    __syncthreads();
    for (int cc=0; cc<8; cc++){
        int c = ty*8+cc;
        float4 acc = make_float4(0.f,0.f,0.f,0.f);
        for (int r=0; r<NPG; r++){
            float a = sAm[r*NPG+c];
            float4 v = st4[r*32 + tx];
            acc.x += a*v.x; acc.y += a*v.y; acc.z += a*v.z; acc.w += a*v.w;
        }
        xqout[(b*64+c)*32 + tx] = acc;
    }
}

// ---------------- cluster score softmax + top-k + outputs ----------------
__global__ void k_topk_score(const float* __restrict__ x, float* __restrict__ out){
    __shared__ float s[64];
    __shared__ float red[64];
    __shared__ int lp[KK];
    int b = blockIdx.x, t = threadIdx.x;
    if (t < 64){ float v = g_f[b*64+t] + g_f[NNODES + b*64+t]; s[t] = v; red[t] = v; }
    __syncthreads();
    for (int o=32; o>0; o>>=1){ if (t<o) red[t] = fmaxf(red[t], red[t+o]); __syncthreads(); }
    float m = red[0];
    __syncthreads();
    if (t < 64){ float e = expf(s[t] - m); s[t] = e; red[t] = e; }
    __syncthreads();
    for (int o=32; o>0; o>>=1){ if (t<o) red[t] += red[t+o]; __syncthreads(); }
    float den = red[0];
    __syncthreads();
    if (t < 64) s[t] = s[t] / den;
    __syncthreads();
    if (t < 64){
        float v = s[t];
        int rank = 0;
        for (int j=0; j<64; j++){
            float u = s[j];
            rank += (u > v) || (u == v && j < t);
        }
        if (rank < KK){
            lp[rank] = t;
            g_perm[b*KK+rank] = b*64+t;
            out[OFF_B + b*KK+rank] = (float)b;
            out[OFF_P + b*KK+rank] = (float)(b*64+t);
        }
    }
    __syncthreads();
    const float4* x4 = (const float4*)x;
    float4* o4 = (float4*)out;
    for (int i=t; i<KK*32; i+=256){
        int r = i >> 5, f = i & 31;
        int p = lp[r];
        float sc = s[p];
        float4 v = x4[(b*64+p)*32 + f];
        o4[(size_t)(b*KK+r)*32 + f] = make_float4(v.x*sc, v.y*sc, v.z*sc, v.w*sc);
    }
}

// ---------------- A2 block triple-product ----------------
__global__ void k_A2(float* __restrict__ out){
    int b = blockIdx.x, t = threadIdx.x;
    __shared__ float sA[NPG*NPG];
    __shared__ float sS[NPG*NPG];
    __shared__ float sU[NPG*KK];
    __shared__ int   sI[KK];
    for (int i=t; i<NPG*NPG; i+=256){ sA[i] = g_A[b*NPG*NPG+i]; sS[i] = g_S[b*NPG*NPG+i]; }
    if (t < KK) sI[t] = g_perm[b*KK+t] - b*NPG;
    __syncthreads();
    for (int idx=t; idx<NPG*KK; idx+=256){
        int r = idx / KK, j = idx - r*KK;
        int pj = sI[j];
        float acc = 0.f;
        for (int c=0; c<NPG; c++) acc += sA[r*NPG+c]*sS[c*NPG+pj];
        sU[idx] = acc;
    }
    __syncthreads();
    for (int idx=t; idx<KK*KK; idx+=256){
        int i2 = idx / KK, j = idx - i2*KK;
        int pi = sI[i2];
        float acc = 0.f;
        for (int r=0; r<NPG; r++) acc += sS[r*NPG+pi]*sU[r*KK+j];
        float v = (i2 == j) ? 1.0f : acc;
        out[(size_t)OFF_A2 + (size_t)(b*KK+i2)*NK + (b*KK+j)] = v;
    }
}

// ---------------- host ----------------
static void launch_attention(int base,
                             const __nv_bfloat16* kvP,
                             const float* q0, const float* q1,
                             const float* W3,
                             __nv_bfloat16* wkP, __nv_bfloat16* w1P,
                             __nv_bfloat16* h0P, __nv_bfloat16* h1P)
{
    k_pgemm<3><<<dim3(1,32,2),256,GSMEM>>>(
        kvP, 0LL, (long long)NNODES*HD,
        wkP + (size_t)base*128*128, 128LL*128, 4LL*128*128,
        128, 128,
        nullptr, 0LL,
        h0P, (long long)NNODES*512, 2LL*NNODES*512,
        q0, q1);
    k_pgemm<2><<<dim3(2,32,2),256,GSMEM>>>(
        h0P, (long long)NNODES*512, 2LL*NNODES*512,
        w1P + (size_t)base*256*512, 256LL*512, 4LL*256*512,
        512, 256,
        nullptr, 0LL,
        h1P, (long long)NNODES*256, 2LL*NNODES*256,
        nullptr, nullptr);
    k_w2s<<<dim3(1,32,2),256,GSMEM>>>(W3, base);
}

extern "C" void kernel_launch(void* const* d_in, const int* in_sizes, int n_in,
                              void* d_out, int out_size)
{
    (void)in_sizes; (void)n_in; (void)out_size;
    const float* x    = (const float*)d_in[0];
    const int*   ei   = (const int*)  d_in[1];
    const float* ew   = (const float*)d_in[2];
    const float* txg  = (const float*)d_in[3];
    const float* Wk   = (const float*)d_in[5];
    const float* W1   = (const float*)d_in[6];
    const float* W2   = (const float*)d_in[7];
    const float* W3   = (const float*)d_in[8];
    const float* linW = (const float*)d_in[9];
    float* out = (float*)d_out;
    const int* row = ei;
    const int* col = ei + NE;

    cudaFuncSetAttribute(k_pgemm<0>, cudaFuncAttributeMaxDynamicSharedMemorySize, GSMEM);
    cudaFuncSetAttribute(k_pgemm<2>, cudaFuncAttributeMaxDynamicSharedMemorySize, GSMEM);
    cudaFuncSetAttribute(k_pgemm<3>, cudaFuncAttributeMaxDynamicSharedMemorySize, GSMEM);
    cudaFuncSetAttribute(k_w2s,     cudaFuncAttributeMaxDynamicSharedMemorySize, GSMEM);
    cudaFuncSetAttribute(k_graph,   cudaFuncAttributeMaxDynamicSharedMemorySize, 98304);
    cudaFuncSetAttribute(k_xc_hop2, cudaFuncAttributeMaxDynamicSharedMemorySize, 81920);

    float *p_xq,*p_qt,*p_P;
    __nv_bfloat16 *p_XP,*p_xcP,*p_aggP,*p_WkP,*p_W1P,*p_LWP,*p_h0P,*p_h1P;
    cudaGetSymbolAddress((void**)&p_xq,   g_xq);
    cudaGetSymbolAddress((void**)&p_qt,   g_qt);
    cudaGetSymbolAddress((void**)&p_P,    g_P);
    cudaGetSymbolAddress((void**)&p_XP,   g_XP);
    cudaGetSymbolAddress((void**)&p_xcP,  g_xcP);
    cudaGetSymbolAddress((void**)&p_aggP, g_aggP);
    cudaGetSymbolAddress((void**)&p_WkP,  g_WkP);
    cudaGetSymbolAddress((void**)&p_W1P,  g_W1P);
    cudaGetSymbolAddress((void**)&p_LWP,  g_LWP);
    cudaGetSymbolAddress((void**)&p_h0P,  g_h0P);
    cudaGetSymbolAddress((void**)&p_h1P,  g_h1P);

    // 1. prep (weight/x splits + qt)
    k_prep<<<(PREP_QT+255)/256,256>>>(Wk, W1, W2, linW, x, txg);
    // 2. graph build + hop^2(x)  (per-batch in smem)
    k_graph<<<NBATCH,256,98304>>>(row, col, ew, x, (float4*)p_xq);
    // 3-5. f1 = att(x, xq); f2 = att(x, qt)
    launch_attention(0, p_XP, p_xq, p_qt, W3, p_WkP, p_W1P, p_h0P, p_h1P);
    // 6. edge softmax -> S + agg planes
    k_edge<<<NBATCH,256>>>(x);
    // 7. P[h] = agg @ lin_W[h]
    k_pgemm<0><<<dim3(1,32,2),256,GSMEM>>>(
        p_aggP, 0LL, (long long)NNODES*HD,
        p_LWP, 128LL*128, 2LL*128*128,
        128, 128,
        p_P, (long long)NNODES*HD,
        nullptr, 0LL, 0LL,
        nullptr, nullptr);
    // 8. xc + split + hop^2
    k_xc_hop2<<<NBATCH,256,81920>>>(x, (float4*)p_xq);
    // 9-11. g1 = att(xc, xq2); g2 = att(xc, qt)
    launch_attention(2, p_xcP, p_xq, p_qt, W3, p_WkP, p_W1P, p_h0P, p_h1P);
    // 12. score softmax + top-k + outputs
    k_topk_score<<<NBATCH,256>>>(x, out);
    // 13-14. A2
    cudaMemsetAsync(out + OFF_A2, 0, (size_t)NK*NK*sizeof(float));
    k_A2<<<NBATCH,256>>>(out);
}

// round 8
// speedup vs baseline: 1.4929x; 1.0607x over previous
#include <cuda_runtime.h>
#include <cuda_bf16.h>
#include <cstdint>

// ---------------- problem constants ----------------
#define NNODES 4096
#define NBATCH 64
#define NPG    64
#define HD     128
#define HD4    32
#define NE     131072
#define EPB    2048          // edges per batch
#define KK     52
#define NK     3328

#define LEN_X  (NK*HD)
#define OFF_A2 (LEN_X)
#define OFF_B  (OFF_A2 + NK*NK)
#define OFF_P  (OFF_B + NK)

// GEMM smem: 2 buffers x (3 planes x 128 rows x 20 u32 per side x 2 sides)
#define ROWU 20
#define PLU  (128*ROWU)
#define BUFU (6*PLU)
#define GSMEM (2*BUFU*4)         // 122880 bytes

// ---------------- scratch ----------------
__device__ float g_A[NBATCH*NPG*NPG];
__device__ float g_Cnt[NBATCH*NPG*NPG];
__device__ float g_S[NBATCH*NPG*NPG];
__device__ float g_xq[NNODES*HD];
__device__ float g_qt[NNODES*HD];
__device__ float g_f[2*NNODES];
__device__ float g_P[2*NNODES*HD];
__device__ int   g_perm[NK];

// bf16 split planes (plane-major), 16B-aligned
__device__ __align__(16) __nv_bfloat16 g_XP  [3*NNODES*HD];
__device__ __align__(16) __nv_bfloat16 g_xcP [3*NNODES*HD];
__device__ __align__(16) __nv_bfloat16 g_aggP[3*NNODES*HD];
__device__ __align__(16) __nv_bfloat16 g_WkP [3*4*128*128];
__device__ __align__(16) __nv_bfloat16 g_W1P [3*4*256*512];
__device__ __align__(16) __nv_bfloat16 g_W2P [3*4*128*256];
__device__ __align__(16) __nv_bfloat16 g_LWP [3*2*128*128];
__device__ __align__(16) __nv_bfloat16 g_h0P [3*2*NNODES*512];
__device__ __align__(16) __nv_bfloat16 g_h1P [3*2*NNODES*256];

__device__ __forceinline__ float lrelu(float v){ return v > 0.f ? v : 0.01f*v; }

__device__ __forceinline__ void split3(float a, unsigned short& h0, unsigned short& h1, unsigned short& h2){
    __nv_bfloat16 b0 = __float2bfloat16(a); float r1 = a - __bfloat162float(b0);
    __nv_bfloat16 b1 = __float2bfloat16(r1); float r2 = r1 - __bfloat162float(b1);
    __nv_bfloat16 b2 = __float2bfloat16(r2);
    h0 = __bfloat16_as_ushort(b0);
    h1 = __bfloat16_as_ushort(b1);
    h2 = __bfloat16_as_ushort(b2);
}
__device__ __forceinline__ void split2pack(float a, float b, uint32_t& p0, uint32_t& p1, uint32_t& p2){
    unsigned short a0,a1,a2,b0,b1,b2;
    split3(a, a0, a1, a2);
    split3(b, b0, b1, b2);
    p0 = (uint32_t)a0 | ((uint32_t)b0 << 16);
    p1 = (uint32_t)a1 | ((uint32_t)b1 << 16);
    p2 = (uint32_t)a2 | ((uint32_t)b2 << 16);
}

__device__ __forceinline__ void mma16816(float* d, const uint32_t* a, const uint32_t* b){
    asm volatile(
        "mma.sync.aligned.m16n8k16.row.col.f32.bf16.bf16.f32 "
        "{%0,%1,%2,%3}, {%4,%5,%6,%7}, {%8,%9}, {%0,%1,%2,%3};"
        : "+f"(d[0]), "+f"(d[1]), "+f"(d[2]), "+f"(d[3])
        : "r"(a[0]), "r"(a[1]), "r"(a[2]), "r"(a[3]), "r"(b[0]), "r"(b[1]));
}

// ---------------- double-buffered mainloop pieces ----------------
#define LOADCHUNK(AP, aZ, aP, BP, bZ, bP, KTOT, K0)                                        \
    _Pragma("unroll")                                                                      \
    for (int p=0; p<3; p++){                                                               \
        const __nv_bfloat16* as = (AP) + (size_t)p*(aP) + (size_t)z*(aZ) + (size_t)(rowBase+fr)*(KTOT) + (K0) + fkh*16; \
        pa[p][0] = *(const uint4*)as;                                                      \
        pa[p][1] = *(const uint4*)(as+8);                                                  \
        const __nv_bfloat16* bs = (BP) + (size_t)p*(bP) + (size_t)z*(bZ) + (size_t)(colBase+fr)*(KTOT) + (K0) + fkh*16; \
        pb[p][0] = *(const uint4*)bs;                                                      \
        pb[p][1] = *(const uint4*)(bs+8);                                                  \
    }

#define STORECHUNK(BUF)                                                                    \
    _Pragma("unroll")                                                                      \
    for (int p=0; p<3; p++){                                                               \
        uint32_t* d = (BUF) + p*PLU + fr*ROWU + fkh*8;                                     \
        d[0]=pa[p][0].x; d[1]=pa[p][0].y; d[2]=pa[p][0].z; d[3]=pa[p][0].w;                \
        d[4]=pa[p][1].x; d[5]=pa[p][1].y; d[6]=pa[p][1].z; d[7]=pa[p][1].w;                \
        uint32_t* db = (BUF) + (3+p)*PLU + fr*ROWU + fkh*8;                                \
        db[0]=pb[p][0].x; db[1]=pb[p][0].y; db[2]=pb[p][0].z; db[3]=pb[p][0].w;            \
        db[4]=pb[p][1].x; db[5]=pb[p][1].y; db[6]=pb[p][1].z; db[7]=pb[p][1].w;            \
    }

#define MMACHUNK(BUF)                                                                      \
    _Pragma("unroll")                                                                      \
    for (int s=0; s<2; s++){                                                               \
        uint32_t bf[3][4][2];                                                              \
        _Pragma("unroll")                                                                  \
        for (int ni=0; ni<4; ni++){                                                        \
            int bbase = (warpN + ni*8 + (lane>>2))*ROWU + s*8 + (lane&3);                  \
            bf[0][ni][0]=(BUF)[3*PLU+bbase]; bf[0][ni][1]=(BUF)[3*PLU+bbase+4];            \
            bf[1][ni][0]=(BUF)[4*PLU+bbase]; bf[1][ni][1]=(BUF)[4*PLU+bbase+4];            \
            bf[2][ni][0]=(BUF)[5*PLU+bbase]; bf[2][ni][1]=(BUF)[5*PLU+bbase+4];            \
        }                                                                                  \
        _Pragma("unroll")                                                                  \
        for (int apl=0; apl<3; apl++){                                                     \
            const uint32_t* As = (BUF) + apl*PLU;                                          \
            uint32_t af[4][4];                                                             \
            _Pragma("unroll")                                                              \
            for (int mi=0; mi<4; mi++){                                                    \
                int abase = (warpM + mi*16 + (lane>>2))*ROWU + s*8 + (lane&3);             \
                af[mi][0]=As[abase];                                                       \
                af[mi][1]=As[abase+8*ROWU];                                                \
                af[mi][2]=As[abase+4];                                                     \
                af[mi][3]=As[abase+8*ROWU+4];                                              \
            }                                                                              \
            int nb = (apl==0)?3:((apl==1)?2:1);                                            \
            _Pragma("unroll")                                                              \
            for (int bpl=0; bpl<3; bpl++){                                                 \
                if (bpl >= nb) break;                                                      \
                _Pragma("unroll")                                                          \
                for (int mi=0; mi<4; mi++)                                                 \
                    _Pragma("unroll")                                                      \
                    for (int ni=0; ni<4; ni++)                                             \
                        mma16816(acc[mi*4+ni], af[mi], bf[bpl][ni]);                       \
            }                                                                              \
        }                                                                                  \
    }

#define GEMM_MAINLOOP(AP, aZ, aP, BP, bZ, bP, KTOT)                                        \
    int chunks = (KTOT) >> 5;                                                              \
    int fr = t >> 1, fkh = t & 1;                                                          \
    uint4 pa[3][2], pb[3][2];                                                              \
    LOADCHUNK(AP, aZ, aP, BP, bZ, bP, KTOT, 0)                                             \
    STORECHUNK(smu)                                                                        \
    __syncthreads();                                                                       \
    for (int c = 0; c < chunks; c++){                                                      \
        uint32_t* cur = smu + (c & 1)*BUFU;                                                \
        uint32_t* nxt = smu + ((c + 1) & 1)*BUFU;                                          \
        if (c + 1 < chunks){ LOADCHUNK(AP, aZ, aP, BP, bZ, bP, KTOT, (c+1) << 5) }         \
        MMACHUNK(cur)                                                                      \
        if (c + 1 < chunks){ STORECHUNK(nxt) }                                             \
        __syncthreads();                                                                   \
    }

// ---------------- pre-split GEMM (EPI 0=fp32, 2=lrelu+split planes, 3=h0 concat) ----------------
template<int EPI>
__global__ void __launch_bounds__(256) k_pgemm(
    const __nv_bfloat16* __restrict__ AP, long long aZ, long long aP,
    const __nv_bfloat16* __restrict__ BP, long long bZ, long long bP,
    int Ktot, int Nc,
    float* __restrict__ Cout, long long cZ,
    __nv_bfloat16* __restrict__ OP, long long oZ, long long oP,
    const float* __restrict__ q0, const float* __restrict__ q1)
{
    extern __shared__ uint32_t smu[];
    int t = threadIdx.x, wid = t >> 5, lane = t & 31;
    int z = blockIdx.z;
    int rowBase = blockIdx.y * 128;
    int colBase = blockIdx.x * 128;
    int warpM = (wid >> 2) * 64;
    int warpN = (wid & 3) * 32;

    float acc[16][4];
#pragma unroll
    for (int i=0;i<16;i++){ acc[i][0]=0.f; acc[i][1]=0.f; acc[i][2]=0.f; acc[i][3]=0.f; }

    GEMM_MAINLOOP(AP, aZ, aP, BP, bZ, bP, Ktot)

#pragma unroll
    for (int mi=0; mi<4; mi++){
#pragma unroll
        for (int ni=0; ni<4; ni++){
            float* d = acc[mi*4+ni];
            int r0 = rowBase + warpM + mi*16 + (lane>>2);
            int c0 = colBase + warpN + ni*8 + (lane&3)*2;
            if (EPI == 0){
                float* cp = Cout + (size_t)z*cZ;
                *(float2*)(cp + (size_t)r0*Nc + c0)     = make_float2(d[0], d[1]);
                *(float2*)(cp + (size_t)(r0+8)*Nc + c0) = make_float2(d[2], d[3]);
            } else if (EPI == 2){
#pragma unroll
                for (int qi=0; qi<2; qi++){
                    int row = r0 + qi*8;
                    float da = lrelu(d[qi*2]), db = lrelu(d[qi*2+1]);
                    uint32_t p0,p1,p2;
                    split2pack(da, db, p0, p1, p2);
                    size_t off = (size_t)z*oZ + (size_t)row*Nc + c0;
                    *(uint32_t*)(OP + off)        = p0;
                    *(uint32_t*)(OP + oP + off)   = p1;
                    *(uint32_t*)(OP + 2*oP + off) = p2;
                }
            } else {   // EPI == 3: h0 concat
                const float* q = z ? q1 : q0;
#pragma unroll
                for (int qi=0; qi<2; qi++){
                    int row = r0 + qi*8;
                    float av = d[qi*2], bv = d[qi*2+1];
                    float qa = q[(size_t)row*128 + c0];
                    float qb = q[(size_t)row*128 + c0 + 1];
                    float sa[4] = {av, qa, av-qa, av*qa};
                    float sb[4] = {bv, qb, bv-qb, bv*qb};
#pragma unroll
                    for (int sec=0; sec<4; sec++){
                        uint32_t p0,p1,p2;
                        split2pack(sa[sec], sb[sec], p0, p1, p2);
                        size_t off = (size_t)z*oZ + (size_t)row*512 + sec*128 + c0;
                        *(uint32_t*)(OP + off)        = p0;
                        *(uint32_t*)(OP + oP + off)   = p1;
                        *(uint32_t*)(OP + 2*oP + off) = p2;
                    }
                }
            }
        }
    }
}

// ---------------- W2 GEMM + W3 dot + per-batch softmax (merged) ----------------
__global__ void __launch_bounds__(256) k_w2s(const float* __restrict__ W3, int base)
{
    extern __shared__ uint32_t smu[];
    __shared__ float sw3[128];
    __shared__ float slog[4][128];
    __shared__ float sl[128];
    __shared__ float sred[128];
    int t = threadIdx.x, wid = t >> 5, lane = t & 31;
    int z = blockIdx.z;
    int rowBase = blockIdx.y * 128;
    int colBase = 0;
    int warpM = (wid >> 2) * 64;
    int warpN = (wid & 3) * 32;

    if (t < 128) sw3[t] = W3[(size_t)(base+z)*128 + t];

    float acc[16][4];
#pragma unroll
    for (int i=0;i<16;i++){ acc[i][0]=0.f; acc[i][1]=0.f; acc[i][2]=0.f; acc[i][3]=0.f; }

    GEMM_MAINLOOP(g_h1P, (long long)NNODES*256, 2LL*NNODES*256,
                  g_W2P + (size_t)base*128*256, 128LL*256, 4LL*128*256, 256)

    // per-row dot with w3 (h2 = lrelu(gemm) first)
#pragma unroll
    for (int mi=0; mi<4; mi++){
        float pr0 = 0.f, pr1 = 0.f;
#pragma unroll
        for (int ni=0; ni<4; ni++){
            float* d = acc[mi*4+ni];
            int c0 = warpN + ni*8 + (lane&3)*2;
            pr0 += sw3[c0]*lrelu(d[0]) + sw3[c0+1]*lrelu(d[1]);
            pr1 += sw3[c0]*lrelu(d[2]) + sw3[c0+1]*lrelu(d[3]);
        }
        pr0 += __shfl_xor_sync(0xffffffffu, pr0, 1);
        pr0 += __shfl_xor_sync(0xffffffffu, pr0, 2);
        pr1 += __shfl_xor_sync(0xffffffffu, pr1, 1);
        pr1 += __shfl_xor_sync(0xffffffffu, pr1, 2);
        if ((lane & 3) == 0){
            int rl = warpM + mi*16 + (lane>>2);
            slog[wid & 3][rl]     = pr0;
            slog[wid & 3][rl + 8] = pr1;
        }
    }
    __syncthreads();
    if (t < 128){
        float v = slog[0][t] + slog[1][t] + slog[2][t] + slog[3][t];
        v = lrelu(v);
        sl[t] = v; sred[t] = v;
    }
    __syncthreads();
    for (int o=32; o>0; o>>=1){ if (t<128 && (t&63)<o) sred[t] = fmaxf(sred[t], sred[t+o]); __syncthreads(); }
    float m = (t < 128) ? sred[t & 64] : 0.f;
    __syncthreads();
    if (t < 128){ float e = expf(sl[t] - m); sl[t] = e; sred[t] = e; }
    __syncthreads();
    for (int o=32; o>0; o>>=1){ if (t<128 && (t&63)<o) sred[t] += sred[t+o]; __syncthreads(); }
    if (t < 128) g_f[(size_t)z*NNODES + rowBase + t] = sl[t] / sred[t & 64];
}

// ---------------- prep: split weights (+transpose), split x, build qt ----------------
#define PREP_WK   65536
#define PREP_W1   (PREP_WK + 524288)
#define PREP_W2   (PREP_W1 + 131072)
#define PREP_LW   (PREP_W2 + 32768)
#define PREP_X    (PREP_LW + 524288)
#define PREP_QT   (PREP_X + 524288)

__global__ void k_prep(const float* __restrict__ Wk, const float* __restrict__ W1,
                       const float* __restrict__ W2, const float* __restrict__ LW,
                       const float* __restrict__ x, const float* __restrict__ txg)
{
    int i = blockIdx.x*blockDim.x + threadIdx.x;
    if (i >= PREP_QT) return;
    unsigned short h0,h1,h2;
    if (i < PREP_WK){
        int z = i >> 14, rem = i & 16383, k = rem >> 7, n = rem & 127;
        split3(Wk[i], h0, h1, h2);
        size_t d = (size_t)(z*128 + n)*128 + k;
        g_WkP[d] = __ushort_as_bfloat16(h0);
        g_WkP[4*16384 + d] = __ushort_as_bfloat16(h1);
        g_WkP[8*16384 + d] = __ushort_as_bfloat16(h2);
    } else if (i < PREP_W1){
        int j = i - PREP_WK;
        int z = j >> 17, rem = j & 131071, k = rem >> 8, n = rem & 255;
        split3(W1[j], h0, h1, h2);
        size_t d = (size_t)(z*256 + n)*512 + k;
        g_W1P[d] = __ushort_as_bfloat16(h0);
        g_W1P[4*131072 + d] = __ushort_as_bfloat16(h1);
        g_W1P[(size_t)8*131072 + d] = __ushort_as_bfloat16(h2);
    } else if (i < PREP_W2){
        int j = i - PREP_W1;
        int z = j >> 15, rem = j & 32767, k = rem >> 7, n = rem & 127;
        split3(W2[j], h0, h1, h2);
        size_t d = (size_t)(z*128 + n)*256 + k;
        g_W2P[d] = __ushort_as_bfloat16(h0);
        g_W2P[4*32768 + d] = __ushort_as_bfloat16(h1);
        g_W2P[8*32768 + d] = __ushort_as_bfloat16(h2);
    } else if (i < PREP_LW){
        int j = i - PREP_W2;
        int z = j >> 14, rem = j & 16383, k = rem >> 7, n = rem & 127;
        split3(LW[j], h0, h1, h2);
        size_t d = (size_t)(z*128 + n)*128 + k;
        g_LWP[d] = __ushort_as_bfloat16(h0);
        g_LWP[2*16384 + d] = __ushort_as_bfloat16(h1);
        g_LWP[4*16384 + d] = __ushort_as_bfloat16(h2);
    } else if (i < PREP_X){
        int j = i - PREP_LW;
        split3(x[j], h0, h1, h2);
        g_XP[j] = __ushort_as_bfloat16(h0);
        g_XP[NNODES*HD + j] = __ushort_as_bfloat16(h1);
        g_XP[2*NNODES*HD + j] = __ushort_as_bfloat16(h2);
    } else {
        int j = i - PREP_X;
        g_qt[j] = txg[((j >> 13) << 7) | (j & 127)];
    }
}

// ---------------- graph build + 2 hops, all per-batch in smem ----------------
__global__ void k_graph(const int* __restrict__ row, const int* __restrict__ col,
                        const float* __restrict__ ew, const float* __restrict__ x,
                        float4* __restrict__ xqout)
{
    extern __shared__ float sh[];
    float* sA   = sh;
    float* sCnt = sh + 4096;
    float* sx   = sh + 8192;
    float* stmp = sh + 16384;
    __shared__ float sdeg[64];
    int b = blockIdx.x, t = threadIdx.x;
    for (int i=t; i<4096; i+=256){ sA[i]=0.f; sCnt[i]=0.f; }
    if (t < 64) sdeg[t] = 1.0f;
    __syncthreads();
    const int* er = row + b*EPB;
    const int* ec = col + b*EPB;
    const float* w = ew + b*EPB;
    for (int i=t; i<EPB; i+=256) atomicAdd(&sdeg[ec[i]&63], w[i]);
    __syncthreads();
    if (t < 64) sdeg[t] = rsqrtf(sdeg[t]);
    __syncthreads();
    for (int i=t; i<EPB; i+=256){
        int r = er[i]&63, c = ec[i]&63;
        atomicAdd(&sA[r*64+c], sdeg[r]*w[i]*sdeg[c]);
        atomicAdd(&sCnt[r*64+c], 1.0f);
    }
    if (t < 64){
        atomicAdd(&sA[t*65], sdeg[t]*sdeg[t]);
        atomicAdd(&sCnt[t*65], 1.0f);
    }
    __syncthreads();
    for (int i=t; i<4096; i+=256){ g_A[b*4096+i] = sA[i]; g_Cnt[b*4096+i] = sCnt[i]; }
    float4* sx4 = (float4*)sx;
    const float4* gx4 = (const float4*)(x + (size_t)b*8192);
    for (int i=t; i<2048; i+=256) sx4[i] = gx4[i];
    __syncthreads();
    int tx = t & 31, ty = t >> 5;
    float4* st4 = (float4*)stmp;
    for (int cc=0; cc<8; cc++){
        int c = ty*8+cc;
        float4 acc = make_float4(0.f,0.f,0.f,0.f);
        for (int r=0; r<64; r++){
            float a = sA[r*64+c];
            float4 v = sx4[r*32+tx];
            acc.x += a*v.x; acc.y += a*v.y; acc.z += a*v.z; acc.w += a*v.w;
        }
        st4[c*32+tx] = acc;
    }
    __syncthreads();
    for (int cc=0; cc<8; cc++){
        int c = ty*8+cc;
        float4 acc = make_float4(0.f,0.f,0.f,0.f);
        for (int r=0; r<64; r++){
            float a = sA[r*64+c];
            float4 v = st4[r*32+tx];
            acc.x += a*v.x; acc.y += a*v.y; acc.z += a*v.z; acc.w += a*v.w;
        }
        xqout[(b*64+c)*32 + tx] = acc;
    }
}

// ---------------- edge softmax + S + agg planes ----------------
__global__ void k_edge(const float* __restrict__ x){
    int b = blockIdx.x, t = threadIdx.x;
    __shared__ float sC[NPG*NPG];
    __shared__ float sL[NPG*NPG];
    __shared__ float sf1[NPG], sf2[NPG], sm_[NPG], sden[NPG];
    for (int i=t; i<NPG*NPG; i+=256) sC[i] = g_Cnt[b*NPG*NPG+i];
    if (t < NPG){ sf1[t] = g_f[b*NPG+t]; sf2[t] = g_f[NNODES + b*NPG+t]; }
    __syncthreads();
    for (int i=t; i<NPG*NPG; i+=256){
        int r = i>>6, c = i&63;
        sL[i] = (sC[i] > 0.f) ? lrelu(sf1[c] + sf2[r]) : -1e30f;
    }
    __syncthreads();
    if (t < NPG){
        float m = -1e30f;
        for (int r=0; r<NPG; r++) m = fmaxf(m, sL[r*NPG+t]);
        float den = 0.f;
        for (int r=0; r<NPG; r++){
            float cc = sC[r*NPG+t];
            if (cc > 0.f) den += cc*expf(sL[r*NPG+t]-m);
        }
        sm_[t] = m; sden[t] = den;
    }
    __syncthreads();
    for (int i=t; i<NPG*NPG; i+=256){
        int c = i & 63;
        float cc = sC[i];
        float s = (cc > 0.f) ? cc*expf(sL[i]-sm_[c])/sden[c] : 0.f;
        sL[i] = s;
        g_S[b*NPG*NPG+i] = s;
    }
    __syncthreads();
    const float4* X4 = (const float4*)x;
    int tx = t & 31, ty = t >> 5;
    for (int cc=0; cc<8; cc++){
        int c = ty*8+cc;
        float4 acc = make_float4(0.f,0.f,0.f,0.f);
        for (int r=0; r<NPG; r++){
            float s = sL[r*NPG+c];
            float4 v = X4[(b*NPG+r)*HD4 + tx];
            acc.x += s*v.x; acc.y += s*v.y; acc.z += s*v.z; acc.w += s*v.w;
        }
        uint32_t pxy0,pxy1,pxy2, pzw0,pzw1,pzw2;
        split2pack(acc.x, acc.y, pxy0, pxy1, pxy2);
        split2pack(acc.z, acc.w, pzw0, pzw1, pzw2);
        size_t base = (size_t)(b*64+c)*128 + tx*4;
        *(uint32_t*)(g_aggP + base)                    = pxy0;
        *(uint32_t*)(g_aggP + base + 2)                = pzw0;
        *(uint32_t*)(g_aggP + NNODES*HD + base)        = pxy1;
        *(uint32_t*)(g_aggP + NNODES*HD + base + 2)    = pzw1;
        *(uint32_t*)(g_aggP + 2*NNODES*HD + base)      = pxy2;
        *(uint32_t*)(g_aggP + 2*NNODES*HD + base + 2)  = pzw2;
    }
}

// ---------------- xc compute + split + hop + hop (merged) ----------------
__global__ void k_xc_hop2(const float* __restrict__ x, float4* __restrict__ xqout){
    extern __shared__ float sh[];
    float* sxc  = sh;
    float* sAm  = sh + 8192;
    float* stmp = sh + 12288;
    int b = blockIdx.x, t = threadIdx.x;
    for (int i=t; i<4096; i+=256) sAm[i] = g_A[b*4096+i];
    for (int i=t; i<4096; i+=256){
        int idx2 = i*2;
        size_t gi = (size_t)b*8192 + idx2;
        float x0 = x[gi], x1 = x[gi+1];
        float p00 = g_P[gi], p01 = g_P[gi+1];
        float p10 = g_P[NNODES*HD + gi], p11 = g_P[NNODES*HD + gi+1];
        float v0 = 0.5f*(lrelu(x0+p00) + lrelu(x0+p10));
        float v1 = 0.5f*(lrelu(x1+p01) + lrelu(x1+p11));
        sxc[idx2] = v0; sxc[idx2+1] = v1;
        uint32_t q0,q1,q2;
        split2pack(v0, v1, q0, q1, q2);
        *(uint32_t*)(g_xcP + gi)                = q0;
        *(uint32_t*)(g_xcP + NNODES*HD + gi)    = q1;
        *(uint32_t*)(g_xcP + 2*NNODES*HD + gi)  = q2;
    }
    __syncthreads();
    int tx = t & 31, ty = t >> 5;
    const float4* sx4 = (const float4*)sxc;
    float4* st4 = (float4*)stmp;
    for (int cc=0; cc<8; cc++){
        int c = ty*8+cc;
        float4 acc = make_float4(0.f,0.f,0.f,0.f);
        for (int r=0; r<NPG; r++){
            float a = sAm[r*NPG+c];
            float4 v = sx4[r*32 + tx];
            acc.x += a*v.x; acc.y += a*v.y; acc.z += a*v.z; acc.w += a*v.w;
        }
        st4[c*32+tx] = acc;
    }
    __syncthreads();
    for (int cc=0; cc<8; cc++){
        int c = ty*8+cc;
        float4 acc = make_float4(0.f,0.f,0.f,0.f);
        for (int r=0; r<NPG; r++){
            float a = sAm[r*NPG+c];
            float4 v = st4[r*32 + tx];
            acc.x += a*v.x; acc.y += a*v.y; acc.z += a*v.z; acc.w += a*v.w;
        }
        xqout[(b*64+c)*32 + tx] = acc;
    }
}

// ---------------- cluster score softmax + top-k + outputs ----------------
__global__ void k_topk_score(const float* __restrict__ x, float* __restrict__ out){
    __shared__ float s[64];
    __shared__ float red[64];
    __shared__ int lp[KK];
    int b = blockIdx.x, t = threadIdx.x;
    if (t < 64){ float v = g_f[b*64+t] + g_f[NNODES + b*64+t]; s[t] = v; red[t] = v; }
    __syncthreads();
    for (int o=32; o>0; o>>=1){ if (t<o) red[t] = fmaxf(red[t], red[t+o]); __syncthreads(); }
    float m = red[0];
    __syncthreads();
    if (t < 64){ float e = expf(s[t] - m); s[t] = e; red[t] = e; }
    __syncthreads();
    for (int o=32; o>0; o>>=1){ if (t<o) red[t] += red[t+o]; __syncthreads(); }
    float den = red[0];
    __syncthreads();
    if (t < 64) s[t] = s[t] / den;
    __syncthreads();
    if (t < 64){
        float v = s[t];
        int rank = 0;
        for (int j=0; j<64; j++){
            float u = s[j];
            rank += (u > v) || (u == v && j < t);
        }
        if (rank < KK){
            lp[rank] = t;
            g_perm[b*KK+rank] = b*64+t;
            out[OFF_B + b*KK+rank] = (float)b;
            out[OFF_P + b*KK+rank] = (float)(b*64+t);
        }
    }
    __syncthreads();
    const float4* x4 = (const float4*)x;
    float4* o4 = (float4*)out;
    for (int i=t; i<KK*32; i+=256){
        int r = i >> 5, f = i & 31;
        int p = lp[r];
        float sc = s[p];
        float4 v = x4[(b*64+p)*32 + f];
        o4[(size_t)(b*KK+r)*32 + f] = make_float4(v.x*sc, v.y*sc, v.z*sc, v.w*sc);
    }
}

// ---------------- A2 block triple-product ----------------
__global__ void k_A2(float* __restrict__ out){
    int b = blockIdx.x, t = threadIdx.x;
    __shared__ float sA[NPG*NPG];
    __shared__ float sS[NPG*NPG];
    __shared__ float sU[NPG*KK];
    __shared__ int   sI[KK];
    for (int i=t; i<NPG*NPG; i+=256){ sA[i] = g_A[b*NPG*NPG+i]; sS[i] = g_S[b*NPG*NPG+i]; }
    if (t < KK) sI[t] = g_perm[b*KK+t] - b*NPG;
    __syncthreads();
    for (int idx=t; idx<NPG*KK; idx+=256){
        int r = idx / KK, j = idx - r*KK;
        int pj = sI[j];
        float acc = 0.f;
        for (int c=0; c<NPG; c++) acc += sA[r*NPG+c]*sS[c*NPG+pj];
        sU[idx] = acc;
    }
    __syncthreads();
    for (int idx=t; idx<KK*KK; idx+=256){
        int i2 = idx / KK, j = idx - i2*KK;
        int pi = sI[i2];
        float acc = 0.f;
        for (int r=0; r<NPG; r++) acc += sS[r*NPG+pi]*sU[r*KK+j];
        float v = (i2 == j) ? 1.0f : acc;
        out[(size_t)OFF_A2 + (size_t)(b*KK+i2)*NK + (b*KK+j)] = v;
    }
}

// ---------------- host ----------------
static void launch_attention(int base,
                             const __nv_bfloat16* kvP,
                             const float* q0, const float* q1,
                             const float* W3,
                             __nv_bfloat16* wkP, __nv_bfloat16* w1P,
                             __nv_bfloat16* h0P, __nv_bfloat16* h1P)
{
    k_pgemm<3><<<dim3(1,32,2),256,GSMEM>>>(
        kvP, 0LL, (long long)NNODES*HD,
        wkP + (size_t)base*128*128, 128LL*128, 4LL*128*128,
        128, 128,
        nullptr, 0LL,
        h0P, (long long)NNODES*512, 2LL*NNODES*512,
        q0, q1);
    k_pgemm<2><<<dim3(2,32,2),256,GSMEM>>>(
        h0P, (long long)NNODES*512, 2LL*NNODES*512,
        w1P + (size_t)base*256*512, 256LL*512, 4LL*256*512,
        512, 256,
        nullptr, 0LL,
        h1P, (long long)NNODES*256, 2LL*NNODES*256,
        nullptr, nullptr);
    k_w2s<<<dim3(1,32,2),256,GSMEM>>>(W3, base);
}

extern "C" void kernel_launch(void* const* d_in, const int* in_sizes, int n_in,
                              void* d_out, int out_size)
{
    (void)in_sizes; (void)n_in; (void)out_size;
    const float* x    = (const float*)d_in[0];
    const int*   ei   = (const int*)  d_in[1];
    const float* ew   = (const float*)d_in[2];
    const float* txg  = (const float*)d_in[3];
    const float* Wk   = (const float*)d_in[5];
    const float* W1   = (const float*)d_in[6];
    const float* W2   = (const float*)d_in[7];
    const float* W3   = (const float*)d_in[8];
    const float* linW = (const float*)d_in[9];
    float* out = (float*)d_out;
    const int* row = ei;
    const int* col = ei + NE;

    cudaFuncSetAttribute(k_pgemm<0>, cudaFuncAttributeMaxDynamicSharedMemorySize, GSMEM);
    cudaFuncSetAttribute(k_pgemm<2>, cudaFuncAttributeMaxDynamicSharedMemorySize, GSMEM);
    cudaFuncSetAttribute(k_pgemm<3>, cudaFuncAttributeMaxDynamicSharedMemorySize, GSMEM);
    cudaFuncSetAttribute(k_w2s,     cudaFuncAttributeMaxDynamicSharedMemorySize, GSMEM);
    cudaFuncSetAttribute(k_graph,   cudaFuncAttributeMaxDynamicSharedMemorySize, 98304);
    cudaFuncSetAttribute(k_xc_hop2, cudaFuncAttributeMaxDynamicSharedMemorySize, 81920);

    float *p_xq,*p_qt,*p_P;
    __nv_bfloat16 *p_XP,*p_xcP,*p_aggP,*p_WkP,*p_W1P,*p_LWP,*p_h0P,*p_h1P;
    cudaGetSymbolAddress((void**)&p_xq,   g_xq);
    cudaGetSymbolAddress((void**)&p_qt,   g_qt);
    cudaGetSymbolAddress((void**)&p_P,    g_P);
    cudaGetSymbolAddress((void**)&p_XP,   g_XP);
    cudaGetSymbolAddress((void**)&p_xcP,  g_xcP);
    cudaGetSymbolAddress((void**)&p_aggP, g_aggP);
    cudaGetSymbolAddress((void**)&p_WkP,  g_WkP);
    cudaGetSymbolAddress((void**)&p_W1P,  g_W1P);
    cudaGetSymbolAddress((void**)&p_LWP,  g_LWP);
    cudaGetSymbolAddress((void**)&p_h0P,  g_h0P);
    cudaGetSymbolAddress((void**)&p_h1P,  g_h1P);

    k_prep<<<(PREP_QT+255)/256,256>>>(Wk, W1, W2, linW, x, txg);
    k_graph<<<NBATCH,256,98304>>>(row, col, ew, x, (float4*)p_xq);
    launch_attention(0, p_XP, p_xq, p_qt, W3, p_WkP, p_W1P, p_h0P, p_h1P);
    k_edge<<<NBATCH,256>>>(x);
    k_pgemm<0><<<dim3(1,32,2),256,GSMEM>>>(
        p_aggP, 0LL, (long long)NNODES*HD,
        p_LWP, 128LL*128, 2LL*128*128,
        128, 128,
        p_P, (long long)NNODES*HD,
        nullptr, 0LL, 0LL,
        nullptr, nullptr);
    k_xc_hop2<<<NBATCH,256,81920>>>(x, (float4*)p_xq);
    launch_attention(2, p_xcP, p_xq, p_qt, W3, p_WkP, p_W1P, p_h0P, p_h1P);
    k_topk_score<<<NBATCH,256>>>(x, out);
    cudaMemsetAsync(out + OFF_A2, 0, (size_t)NK*NK*sizeof(float));
    k_A2<<<NBATCH,256>>>(out);
}

// round 9
// speedup vs baseline: 1.5507x; 1.0387x over previous
#include <cuda_runtime.h>
#include <cuda_bf16.h>
#include <cstdint>

// ---------------- problem constants ----------------
#define NNODES 4096
#define NBATCH 64
#define NPG    64
#define HD     128
#define HD4    32
#define NE     131072
#define EPB    2048
#define KK     52
#define NK     3328
#define NK4    (NK/4)

#define LEN_X  (NK*HD)
#define OFF_A2 (LEN_X)
#define OFF_B  (OFF_A2 + NK*NK)
#define OFF_P  (OFF_B + NK)

// GEMM smem: 2 buffers x (3 planes x 128 rows x 20 u32 per side x 2 sides)
#define ROWU 20
#define PLU  (128*ROWU)
#define BUFU (6*PLU)
#define GSMEM (2*BUFU*4)         // 122880 bytes

// ---------------- scratch ----------------
__device__ float g_A[NBATCH*NPG*NPG];
__device__ float g_Cnt[NBATCH*NPG*NPG];
__device__ float g_S[NBATCH*NPG*NPG];
__device__ float g_xq[NNODES*HD];
__device__ float g_qt[NNODES*HD];
__device__ float g_f[2*NNODES];
__device__ float g_P[2*NNODES*HD];

// bf16 split planes (plane-major), 16B-aligned
__device__ __align__(16) __nv_bfloat16 g_XP  [3*NNODES*HD];
__device__ __align__(16) __nv_bfloat16 g_xcP [3*NNODES*HD];
__device__ __align__(16) __nv_bfloat16 g_aggP[3*NNODES*HD];
__device__ __align__(16) __nv_bfloat16 g_WkP [3*4*128*128];
__device__ __align__(16) __nv_bfloat16 g_W1P [3*4*256*512];
__device__ __align__(16) __nv_bfloat16 g_W2P [3*4*128*256];
__device__ __align__(16) __nv_bfloat16 g_LWP [3*2*128*128];
__device__ __align__(16) __nv_bfloat16 g_h0P [3*2*NNODES*512];
__device__ __align__(16) __nv_bfloat16 g_h1P [3*2*NNODES*256];

__device__ __forceinline__ float lrelu(float v){ return v > 0.f ? v : 0.01f*v; }

__device__ __forceinline__ void split3(float a, unsigned short& h0, unsigned short& h1, unsigned short& h2){
    __nv_bfloat16 b0 = __float2bfloat16(a); float r1 = a - __bfloat162float(b0);
    __nv_bfloat16 b1 = __float2bfloat16(r1); float r2 = r1 - __bfloat162float(b1);
    __nv_bfloat16 b2 = __float2bfloat16(r2);
    h0 = __bfloat16_as_ushort(b0);
    h1 = __bfloat16_as_ushort(b1);
    h2 = __bfloat16_as_ushort(b2);
}
__device__ __forceinline__ void split2pack(float a, float b, uint32_t& p0, uint32_t& p1, uint32_t& p2){
    unsigned short a0,a1,a2,b0,b1,b2;
    split3(a, a0, a1, a2);
    split3(b, b0, b1, b2);
    p0 = (uint32_t)a0 | ((uint32_t)b0 << 16);
    p1 = (uint32_t)a1 | ((uint32_t)b1 << 16);
    p2 = (uint32_t)a2 | ((uint32_t)b2 << 16);
}

__device__ __forceinline__ void mma16816(float* d, const uint32_t* a, const uint32_t* b){
    asm volatile(
        "mma.sync.aligned.m16n8k16.row.col.f32.bf16.bf16.f32 "
        "{%0,%1,%2,%3}, {%4,%5,%6,%7}, {%8,%9}, {%0,%1,%2,%3};"
        : "+f"(d[0]), "+f"(d[1]), "+f"(d[2]), "+f"(d[3])
        : "r"(a[0]), "r"(a[1]), "r"(a[2]), "r"(a[3]), "r"(b[0]), "r"(b[1]));
}

__device__ __forceinline__ void ldm4(uint32_t* r, uint32_t addr){
    asm volatile("ldmatrix.sync.aligned.m8n8.x4.shared.b16 {%0,%1,%2,%3}, [%4];"
        : "=r"(r[0]), "=r"(r[1]), "=r"(r[2]), "=r"(r[3]) : "r"(addr));
}

// ---------------- double-buffered mainloop pieces ----------------
#define LOADCHUNK(AP, aZ, aP, BP, bZ, bP, KTOT, K0)                                        \
    _Pragma("unroll")                                                                      \
    for (int p=0; p<3; p++){                                                               \
        const __nv_bfloat16* as = (AP) + (size_t)p*(aP) + (size_t)z*(aZ) + (size_t)(rowBase+fr)*(KTOT) + (K0) + fkh*16; \
        pa[p][0] = *(const uint4*)as;                                                      \
        pa[p][1] = *(const uint4*)(as+8);                                                  \
        const __nv_bfloat16* bs = (BP) + (size_t)p*(bP) + (size_t)z*(bZ) + (size_t)(colBase+fr)*(KTOT) + (K0) + fkh*16; \
        pb[p][0] = *(const uint4*)bs;                                                      \
        pb[p][1] = *(const uint4*)(bs+8);                                                  \
    }

#define STORECHUNK(BUF)                                                                    \
    _Pragma("unroll")                                                                      \
    for (int p=0; p<3; p++){                                                               \
        uint32_t* d = (BUF) + p*PLU + fr*ROWU + fkh*8;                                     \
        d[0]=pa[p][0].x; d[1]=pa[p][0].y; d[2]=pa[p][0].z; d[3]=pa[p][0].w;                \
        d[4]=pa[p][1].x; d[5]=pa[p][1].y; d[6]=pa[p][1].z; d[7]=pa[p][1].w;                \
        uint32_t* db = (BUF) + (3+p)*PLU + fr*ROWU + fkh*8;                                \
        db[0]=pb[p][0].x; db[1]=pb[p][0].y; db[2]=pb[p][0].z; db[3]=pb[p][0].w;            \
        db[4]=pb[p][1].x; db[5]=pb[p][1].y; db[6]=pb[p][1].z; db[7]=pb[p][1].w;            \
    }

// ldmatrix-based MMA stage. BUFB = byte offset of the active buffer.
#define MMACHUNK(BUFB)                                                                     \
    _Pragma("unroll")                                                                      \
    for (int s=0; s<2; s++){                                                               \
        uint32_t bf[3][4][2];                                                              \
        _Pragma("unroll")                                                                  \
        for (int p=0; p<3; p++){                                                           \
            _Pragma("unroll")                                                              \
            for (int pi=0; pi<2; pi++){                                                    \
                uint32_t r4[4];                                                            \
                ldm4(r4, sbb + (BUFB) + (3+p)*(PLU*4) + bRowBase + pi*(16*ROWU*4) + s*32); \
                bf[p][2*pi][0]=r4[0];   bf[p][2*pi][1]=r4[1];                              \
                bf[p][2*pi+1][0]=r4[2]; bf[p][2*pi+1][1]=r4[3];                            \
            }                                                                              \
        }                                                                                  \
        _Pragma("unroll")                                                                  \
        for (int apl=0; apl<3; apl++){                                                     \
            uint32_t af[4][4];                                                             \
            _Pragma("unroll")                                                              \
            for (int mi=0; mi<4; mi++)                                                     \
                ldm4(af[mi], sbb + (BUFB) + apl*(PLU*4) + aRowBase + mi*(16*ROWU*4) + s*32);\
            int nb = (apl==0)?3:((apl==1)?2:1);                                            \
            _Pragma("unroll")                                                              \
            for (int bpl=0; bpl<3; bpl++){                                                 \
                if (bpl >= nb) break;                                                      \
                _Pragma("unroll")                                                          \
                for (int mi=0; mi<4; mi++)                                                 \
                    _Pragma("unroll")                                                      \
                    for (int ni=0; ni<4; ni++)                                             \
                        mma16816(acc[mi*4+ni], af[mi], bf[bpl][ni]);                       \
            }                                                                              \
        }                                                                                  \
    }

#define GEMM_MAINLOOP(AP, aZ, aP, BP, bZ, bP, KTOT)                                        \
    int chunks = (KTOT) >> 5;                                                              \
    int fr = t >> 1, fkh = t & 1;                                                          \
    uint32_t sbb;                                                                          \
    asm("{ .reg .u64 tt; cvta.to.shared.u64 tt, %1; cvt.u32.u64 %0, tt; }" : "=r"(sbb) : "l"(smu)); \
    int quad = lane >> 3, qi = lane & 7;                                                   \
    uint32_t aRowBase = (uint32_t)(warpM + (quad&1)*8 + qi)*(ROWU*4) + (quad>>1)*16;       \
    uint32_t bRowBase = (uint32_t)(warpN + (quad>>1)*8 + qi)*(ROWU*4) + (quad&1)*16;       \
    uint4 pa[3][2], pb[3][2];                                                              \
    LOADCHUNK(AP, aZ, aP, BP, bZ, bP, KTOT, 0)                                             \
    STORECHUNK(smu)                                                                        \
    __syncthreads();                                                                       \
    for (int c = 0; c < chunks; c++){                                                      \
        uint32_t curB = (uint32_t)(c & 1)*(BUFU*4);                                        \
        uint32_t* nxt = smu + ((c + 1) & 1)*BUFU;                                          \
        if (c + 1 < chunks){ LOADCHUNK(AP, aZ, aP, BP, bZ, bP, KTOT, (c+1) << 5) }         \
        MMACHUNK(curB)                                                                     \
        if (c + 1 < chunks){ STORECHUNK(nxt) }                                             \
        __syncthreads();                                                                   \
    }

// ---------------- pre-split GEMM (EPI 0=fp32, 2=lrelu+split planes, 3=h0 concat) ----------------
template<int EPI>
__global__ void __launch_bounds__(256) k_pgemm(
    const __nv_bfloat16* __restrict__ AP, long long aZ, long long aP,
    const __nv_bfloat16* __restrict__ BP, long long bZ, long long bP,
    int Ktot, int Nc,
    float* __restrict__ Cout, long long cZ,
    __nv_bfloat16* __restrict__ OP, long long oZ, long long oP,
    const float* __restrict__ q0, const float* __restrict__ q1)
{
    extern __shared__ uint32_t smu[];
    int t = threadIdx.x, wid = t >> 5, lane = t & 31;
    int z = blockIdx.z;
    int rowBase = blockIdx.y * 128;
    int colBase = blockIdx.x * 128;
    int warpM = (wid >> 2) * 64;
    int warpN = (wid & 3) * 32;

    float acc[16][4];
#pragma unroll
    for (int i=0;i<16;i++){ acc[i][0]=0.f; acc[i][1]=0.f; acc[i][2]=0.f; acc[i][3]=0.f; }

    GEMM_MAINLOOP(AP, aZ, aP, BP, bZ, bP, Ktot)

#pragma unroll
    for (int mi=0; mi<4; mi++){
#pragma unroll
        for (int ni=0; ni<4; ni++){
            float* d = acc[mi*4+ni];
            int r0 = rowBase + warpM + mi*16 + (lane>>2);
            int c0 = colBase + warpN + ni*8 + (lane&3)*2;
            if (EPI == 0){
                float* cp = Cout + (size_t)z*cZ;
                *(float2*)(cp + (size_t)r0*Nc + c0)     = make_float2(d[0], d[1]);
                *(float2*)(cp + (size_t)(r0+8)*Nc + c0) = make_float2(d[2], d[3]);
            } else if (EPI == 2){
#pragma unroll
                for (int qi2=0; qi2<2; qi2++){
                    int row = r0 + qi2*8;
                    float da = lrelu(d[qi2*2]), db = lrelu(d[qi2*2+1]);
                    uint32_t p0,p1,p2;
                    split2pack(da, db, p0, p1, p2);
                    size_t off = (size_t)z*oZ + (size_t)row*Nc + c0;
                    *(uint32_t*)(OP + off)        = p0;
                    *(uint32_t*)(OP + oP + off)   = p1;
                    *(uint32_t*)(OP + 2*oP + off) = p2;
                }
            } else {   // EPI == 3: h0 concat
                const float* q = z ? q1 : q0;
#pragma unroll
                for (int qi2=0; qi2<2; qi2++){
                    int row = r0 + qi2*8;
                    float av = d[qi2*2], bv = d[qi2*2+1];
                    float qa = q[(size_t)row*128 + c0];
                    float qb = q[(size_t)row*128 + c0 + 1];
                    float sa[4] = {av, qa, av-qa, av*qa};
                    float sb[4] = {bv, qb, bv-qb, bv*qb};
#pragma unroll
                    for (int sec=0; sec<4; sec++){
                        uint32_t p0,p1,p2;
                        split2pack(sa[sec], sb[sec], p0, p1, p2);
                        size_t off = (size_t)z*oZ + (size_t)row*512 + sec*128 + c0;
                        *(uint32_t*)(OP + off)        = p0;
                        *(uint32_t*)(OP + oP + off)   = p1;
                        *(uint32_t*)(OP + 2*oP + off) = p2;
                    }
                }
            }
        }
    }
}

// ---------------- W2 GEMM + W3 dot + per-batch softmax (merged) ----------------
__global__ void __launch_bounds__(256) k_w2s(const float* __restrict__ W3, int base)
{
    extern __shared__ uint32_t smu[];
    __shared__ float sw3[128];
    __shared__ float slog[4][128];
    __shared__ float sl[128];
    __shared__ float sred[128];
    int t = threadIdx.x, wid = t >> 5, lane = t & 31;
    int z = blockIdx.z;
    int rowBase = blockIdx.y * 128;
    int colBase = 0;
    int warpM = (wid >> 2) * 64;
    int warpN = (wid & 3) * 32;

    if (t < 128) sw3[t] = W3[(size_t)(base+z)*128 + t];

    float acc[16][4];
#pragma unroll
    for (int i=0;i<16;i++){ acc[i][0]=0.f; acc[i][1]=0.f; acc[i][2]=0.f; acc[i][3]=0.f; }

    GEMM_MAINLOOP(g_h1P, (long long)NNODES*256, 2LL*NNODES*256,
                  g_W2P + (size_t)base*128*256, 128LL*256, 4LL*128*256, 256)

#pragma unroll
    for (int mi=0; mi<4; mi++){
        float pr0 = 0.f, pr1 = 0.f;
#pragma unroll
        for (int ni=0; ni<4; ni++){
            float* d = acc[mi*4+ni];
            int c0 = warpN + ni*8 + (lane&3)*2;
            pr0 += sw3[c0]*lrelu(d[0]) + sw3[c0+1]*lrelu(d[1]);
            pr1 += sw3[c0]*lrelu(d[2]) + sw3[c0+1]*lrelu(d[3]);
        }
        pr0 += __shfl_xor_sync(0xffffffffu, pr0, 1);
        pr0 += __shfl_xor_sync(0xffffffffu, pr0, 2);
        pr1 += __shfl_xor_sync(0xffffffffu, pr1, 1);
        pr1 += __shfl_xor_sync(0xffffffffu, pr1, 2);
        if ((lane & 3) == 0){
            int rl = warpM + mi*16 + (lane>>2);
            slog[wid & 3][rl]     = pr0;
            slog[wid & 3][rl + 8] = pr1;
        }
    }
    __syncthreads();
    if (t < 128){
        float v = slog[0][t] + slog[1][t] + slog[2][t] + slog[3][t];
        v = lrelu(v);
        sl[t] = v; sred[t] = v;
    }
    __syncthreads();
    for (int o=32; o>0; o>>=1){ if (t<128 && (t&63)<o) sred[t] = fmaxf(sred[t], sred[t+o]); __syncthreads(); }
    float m = (t < 128) ? sred[t & 64] : 0.f;
    __syncthreads();
    if (t < 128){ float e = expf(sl[t] - m); sl[t] = e; sred[t] = e; }
    __syncthreads();
    for (int o=32; o>0; o>>=1){ if (t<128 && (t&63)<o) sred[t] += sred[t+o]; __syncthreads(); }
    if (t < 128) g_f[(size_t)z*NNODES + rowBase + t] = sl[t] / sred[t & 64];
}

// ---------------- merged prep + graph ----------------
#define PREP_WK   65536
#define PREP_W1   (PREP_WK + 524288)
#define PREP_W2   (PREP_W1 + 131072)
#define PREP_LW   (PREP_W2 + 32768)
#define PREP_X    (PREP_LW + 524288)
#define PREP_QT   (PREP_X + 524288)
#define PREP_BLOCKS 256

__global__ void k_prep_graph(
    const float* __restrict__ Wk, const float* __restrict__ W1,
    const float* __restrict__ W2, const float* __restrict__ LW,
    const float* __restrict__ x, const float* __restrict__ txg,
    const int* __restrict__ row, const int* __restrict__ col,
    const float* __restrict__ ew, float4* __restrict__ xqout)
{
    int t = threadIdx.x;
    if (blockIdx.x >= NBATCH){
        // -------- prep path (grid-strided) --------
        for (int i = (blockIdx.x - NBATCH)*256 + t; i < PREP_QT; i += PREP_BLOCKS*256){
            unsigned short h0,h1,h2;
            if (i < PREP_WK){
                int z = i >> 14, rem = i & 16383, k = rem >> 7, n = rem & 127;
                split3(Wk[i], h0, h1, h2);
                size_t d = (size_t)(z*128 + n)*128 + k;
                g_WkP[d] = __ushort_as_bfloat16(h0);
                g_WkP[4*16384 + d] = __ushort_as_bfloat16(h1);
                g_WkP[8*16384 + d] = __ushort_as_bfloat16(h2);
            } else if (i < PREP_W1){
                int j = i - PREP_WK;
                int z = j >> 17, rem = j & 131071, k = rem >> 8, n = rem & 255;
                split3(W1[j], h0, h1, h2);
                size_t d = (size_t)(z*256 + n)*512 + k;
                g_W1P[d] = __ushort_as_bfloat16(h0);
                g_W1P[4*131072 + d] = __ushort_as_bfloat16(h1);
                g_W1P[(size_t)8*131072 + d] = __ushort_as_bfloat16(h2);
            } else if (i < PREP_W2){
                int j = i - PREP_W1;
                int z = j >> 15, rem = j & 32767, k = rem >> 7, n = rem & 127;
                split3(W2[j], h0, h1, h2);
                size_t d = (size_t)(z*128 + n)*256 + k;
                g_W2P[d] = __ushort_as_bfloat16(h0);
                g_W2P[4*32768 + d] = __ushort_as_bfloat16(h1);
                g_W2P[8*32768 + d] = __ushort_as_bfloat16(h2);
            } else if (i < PREP_LW){
                int j = i - PREP_W2;
                int z = j >> 14, rem = j & 16383, k = rem >> 7, n = rem & 127;
                split3(LW[j], h0, h1, h2);
                size_t d = (size_t)(z*128 + n)*128 + k;
                g_LWP[d] = __ushort_as_bfloat16(h0);
                g_LWP[2*16384 + d] = __ushort_as_bfloat16(h1);
                g_LWP[4*16384 + d] = __ushort_as_bfloat16(h2);
            } else if (i < PREP_X){
                int j = i - PREP_LW;
                split3(x[j], h0, h1, h2);
                g_XP[j] = __ushort_as_bfloat16(h0);
                g_XP[NNODES*HD + j] = __ushort_as_bfloat16(h1);
                g_XP[2*NNODES*HD + j] = __ushort_as_bfloat16(h2);
            } else {
                int j = i - PREP_X;
                g_qt[j] = txg[((j >> 13) << 7) | (j & 127)];
            }
        }
        return;
    }
    // -------- graph path: build A/Cnt + hop^2(x), per-batch in smem --------
    extern __shared__ float sh[];
    float* sA   = sh;
    float* sCnt = sh + 4096;
    float* sx   = sh + 8192;
    float* stmp = sh + 16384;
    __shared__ float sdeg[64];
    int b = blockIdx.x;
    for (int i=t; i<4096; i+=256){ sA[i]=0.f; sCnt[i]=0.f; }
    if (t < 64) sdeg[t] = 1.0f;
    __syncthreads();
    const int* er = row + b*EPB;
    const int* ec = col + b*EPB;
    const float* w = ew + b*EPB;
    for (int i=t; i<EPB; i+=256) atomicAdd(&sdeg[ec[i]&63], w[i]);
    __syncthreads();
    if (t < 64) sdeg[t] = rsqrtf(sdeg[t]);
    __syncthreads();
    for (int i=t; i<EPB; i+=256){
        int r = er[i]&63, c = ec[i]&63;
        atomicAdd(&sA[r*64+c], sdeg[r]*w[i]*sdeg[c]);
        atomicAdd(&sCnt[r*64+c], 1.0f);
    }
    if (t < 64){
        atomicAdd(&sA[t*65], sdeg[t]*sdeg[t]);
        atomicAdd(&sCnt[t*65], 1.0f);
    }
    __syncthreads();
    for (int i=t; i<4096; i+=256){ g_A[b*4096+i] = sA[i]; g_Cnt[b*4096+i] = sCnt[i]; }
    float4* sx4 = (float4*)sx;
    const float4* gx4 = (const float4*)(x + (size_t)b*8192);
    for (int i=t; i<2048; i+=256) sx4[i] = gx4[i];
    __syncthreads();
    int tx = t & 31, ty = t >> 5;
    float4* st4 = (float4*)stmp;
    for (int cc=0; cc<8; cc++){
        int c = ty*8+cc;
        float4 acc = make_float4(0.f,0.f,0.f,0.f);
        for (int r=0; r<64; r++){
            float a = sA[r*64+c];
            float4 v = sx4[r*32+tx];
            acc.x += a*v.x; acc.y += a*v.y; acc.z += a*v.z; acc.w += a*v.w;
        }
        st4[c*32+tx] = acc;
    }
    __syncthreads();
    for (int cc=0; cc<8; cc++){
        int c = ty*8+cc;
        float4 acc = make_float4(0.f,0.f,0.f,0.f);
        for (int r=0; r<64; r++){
            float a = sA[r*64+c];
            float4 v = st4[r*32+tx];
            acc.x += a*v.x; acc.y += a*v.y; acc.z += a*v.z; acc.w += a*v.w;
        }
        xqout[(b*64+c)*32 + tx] = acc;
    }
}

// ---------------- edge softmax + S + agg planes ----------------
__global__ void k_edge(const float* __restrict__ x){
    int b = blockIdx.x, t = threadIdx.x;
    __shared__ float sC[NPG*NPG];
    __shared__ float sL[NPG*NPG];
    __shared__ float sf1[NPG], sf2[NPG], sm_[NPG], sden[NPG];
    for (int i=t; i<NPG*NPG; i+=256) sC[i] = g_Cnt[b*NPG*NPG+i];
    if (t < NPG){ sf1[t] = g_f[b*NPG+t]; sf2[t] = g_f[NNODES + b*NPG+t]; }
    __syncthreads();
    for (int i=t; i<NPG*NPG; i+=256){
        int r = i>>6, c = i&63;
        sL[i] = (sC[i] > 0.f) ? lrelu(sf1[c] + sf2[r]) : -1e30f;
    }
    __syncthreads();
    if (t < NPG){
        float m = -1e30f;
        for (int r=0; r<NPG; r++) m = fmaxf(m, sL[r*NPG+t]);
        float den = 0.f;
        for (int r=0; r<NPG; r++){
            float cc = sC[r*NPG+t];
            if (cc > 0.f) den += cc*expf(sL[r*NPG+t]-m);
        }
        sm_[t] = m; sden[t] = den;
    }
    __syncthreads();
    for (int i=t; i<NPG*NPG; i+=256){
        int c = i & 63;
        float cc = sC[i];
        float s = (cc > 0.f) ? cc*expf(sL[i]-sm_[c])/sden[c] : 0.f;
        sL[i] = s;
        g_S[b*NPG*NPG+i] = s;
    }
    __syncthreads();
    const float4* X4 = (const float4*)x;
    int tx = t & 31, ty = t >> 5;
    for (int cc=0; cc<8; cc++){
        int c = ty*8+cc;
        float4 acc = make_float4(0.f,0.f,0.f,0.f);
        for (int r=0; r<NPG; r++){
            float s = sL[r*NPG+c];
            float4 v = X4[(b*NPG+r)*HD4 + tx];
            acc.x += s*v.x; acc.y += s*v.y; acc.z += s*v.z; acc.w += s*v.w;
        }
        uint32_t pxy0,pxy1,pxy2, pzw0,pzw1,pzw2;
        split2pack(acc.x, acc.y, pxy0, pxy1, pxy2);
        split2pack(acc.z, acc.w, pzw0, pzw1, pzw2);
        size_t base = (size_t)(b*64+c)*128 + tx*4;
        *(uint32_t*)(g_aggP + base)                    = pxy0;
        *(uint32_t*)(g_aggP + base + 2)                = pzw0;
        *(uint32_t*)(g_aggP + NNODES*HD + base)        = pxy1;
        *(uint32_t*)(g_aggP + NNODES*HD + base + 2)    = pzw1;
        *(uint32_t*)(g_aggP + 2*NNODES*HD + base)      = pxy2;
        *(uint32_t*)(g_aggP + 2*NNODES*HD + base + 2)  = pzw2;
    }
}

// ---------------- xc compute + split + hop + hop (merged) ----------------
__global__ void k_xc_hop2(const float* __restrict__ x, float4* __restrict__ xqout){
    extern __shared__ float sh[];
    float* sxc  = sh;
    float* sAm  = sh + 8192;
    float* stmp = sh + 12288;
    int b = blockIdx.x, t = threadIdx.x;
    for (int i=t; i<4096; i+=256) sAm[i] = g_A[b*4096+i];
    for (int i=t; i<4096; i+=256){
        int idx2 = i*2;
        size_t gi = (size_t)b*8192 + idx2;
        float x0 = x[gi], x1 = x[gi+1];
        float p00 = g_P[gi], p01 = g_P[gi+1];
        float p10 = g_P[NNODES*HD + gi], p11 = g_P[NNODES*HD + gi+1];
        float v0 = 0.5f*(lrelu(x0+p00) + lrelu(x0+p10));
        float v1 = 0.5f*(lrelu(x1+p01) + lrelu(x1+p11));
        sxc[idx2] = v0; sxc[idx2+1] = v1;
        uint32_t q0,q1,q2;
        split2pack(v0, v1, q0, q1, q2);
        *(uint32_t*)(g_xcP + gi)                = q0;
        *(uint32_t*)(g_xcP + NNODES*HD + gi)    = q1;
        *(uint32_t*)(g_xcP + 2*NNODES*HD + gi)  = q2;
    }
    __syncthreads();
    int tx = t & 31, ty = t >> 5;
    const float4* sx4 = (const float4*)sxc;
    float4* st4 = (float4*)stmp;
    for (int cc=0; cc<8; cc++){
        int c = ty*8+cc;
        float4 acc = make_float4(0.f,0.f,0.f,0.f);
        for (int r=0; r<NPG; r++){
            float a = sAm[r*NPG+c];
            float4 v = sx4[r*32 + tx];
            acc.x += a*v.x; acc.y += a*v.y; acc.z += a*v.z; acc.w += a*v.w;
        }
        st4[c*32+tx] = acc;
    }
    __syncthreads();
    for (int cc=0; cc<8; cc++){
        int c = ty*8+cc;
        float4 acc = make_float4(0.f,0.f,0.f,0.f);
        for (int r=0; r<NPG; r++){
            float a = sAm[r*NPG+c];
            float4 v = st4[r*32 + tx];
            acc.x += a*v.x; acc.y += a*v.y; acc.z += a*v.z; acc.w += a*v.w;
        }
        xqout[(b*64+c)*32 + tx] = acc;
    }
}

// ---------------- score softmax + top-k + x_out/batch/perm + A2 stripe (merged) ----------------
__global__ void k_topkA2(const float* __restrict__ x, float* __restrict__ out){
    __shared__ float sA[NPG*NPG];
    __shared__ float sS[NPG*NPG];
    __shared__ float sU[NPG*KK];
    __shared__ float s[64];
    __shared__ float red[64];
    __shared__ int lp[KK];
    int b = blockIdx.x, t = threadIdx.x;
    // softmax of (f1+f2)
    if (t < 64){ float v = g_f[b*64+t] + g_f[NNODES + b*64+t]; s[t] = v; red[t] = v; }
    __syncthreads();
    for (int o=32; o>0; o>>=1){ if (t<o) red[t] = fmaxf(red[t], red[t+o]); __syncthreads(); }
    float m = red[0];
    __syncthreads();
    if (t < 64){ float e = expf(s[t] - m); s[t] = e; red[t] = e; }
    __syncthreads();
    for (int o=32; o>0; o>>=1){ if (t<o) red[t] += red[t+o]; __syncthreads(); }
    float den = red[0];
    __syncthreads();
    if (t < 64) s[t] = s[t] / den;
    __syncthreads();
    // stable descending top-k
    if (t < 64){
        float v = s[t];
        int rank = 0;
        for (int j=0; j<64; j++){
            float u = s[j];
            rank += (u > v) || (u == v && j < t);
        }
        if (rank < KK){
            lp[rank] = t;
            out[OFF_B + b*KK+rank] = (float)b;
            out[OFF_P + b*KK+rank] = (float)(b*64+t);
        }
    }
    __syncthreads();
    // x_out
    {
        const float4* x4 = (const float4*)x;
        float4* o4 = (float4*)out;
        for (int i=t; i<KK*32; i+=256){
            int r = i >> 5, f = i & 31;
            int p = lp[r];
            float sc = s[p];
            float4 v = x4[(b*64+p)*32 + f];
            o4[(size_t)(b*KK+r)*32 + f] = make_float4(v.x*sc, v.y*sc, v.z*sc, v.w*sc);
        }
    }
    // zero-fill this block's 52-row stripe of A2 (replaces global memset)
    {
        float4 z4 = make_float4(0.f,0.f,0.f,0.f);
        float4* a4 = (float4*)(out + OFF_A2);
        for (int idx=t; idx<KK*NK4; idx+=256){
            int i2 = idx / NK4, c4 = idx - i2*NK4;
            a4[(size_t)(b*KK+i2)*NK4 + c4] = z4;
        }
    }
    // load A, S
    for (int i=t; i<NPG*NPG; i+=256){ sA[i] = g_A[b*NPG*NPG+i]; sS[i] = g_S[b*NPG*NPG+i]; }
    __syncthreads();
    // U[r][j] = sum_c A[r][c] * S[c][pj]
    for (int idx=t; idx<NPG*KK; idx+=256){
        int r = idx / KK, j = idx - r*KK;
        int pj = lp[j];
        float acc = 0.f;
        for (int c=0; c<NPG; c++) acc += sA[r*NPG+c]*sS[c*NPG+pj];
        sU[idx] = acc;
    }
    __syncthreads();
    // V[i][j] = sum_r S[r][pi] * U[r][j]; diag -> 1
    for (int idx=t; idx<KK*KK; idx+=256){
        int i2 = idx / KK, j = idx - i2*KK;
        int pi = lp[i2];
        float acc = 0.f;
        for (int r=0; r<NPG; r++) acc += sS[r*NPG+pi]*sU[r*KK+j];
        float v = (i2 == j) ? 1.0f : acc;
        out[(size_t)OFF_A2 + (size_t)(b*KK+i2)*NK + (b*KK+j)] = v;
    }
}

// ---------------- host ----------------
static void launch_attention(int base,
                             const __nv_bfloat16* kvP,
                             const float* q0, const float* q1,
                             const float* W3,
                             __nv_bfloat16* wkP, __nv_bfloat16* w1P,
                             __nv_bfloat16* h0P, __nv_bfloat16* h1P)
{
    k_pgemm<3><<<dim3(1,32,2),256,GSMEM>>>(
        kvP, 0LL, (long long)NNODES*HD,
        wkP + (size_t)base*128*128, 128LL*128, 4LL*128*128,
        128, 128,
        nullptr, 0LL,
        h0P, (long long)NNODES*512, 2LL*NNODES*512,
        q0, q1);
    k_pgemm<2><<<dim3(2,32,2),256,GSMEM>>>(
        h0P, (long long)NNODES*512, 2LL*NNODES*512,
        w1P + (size_t)base*256*512, 256LL*512, 4LL*256*512,
        512, 256,
        nullptr, 0LL,
        h1P, (long long)NNODES*256, 2LL*NNODES*256,
        nullptr, nullptr);
    k_w2s<<<dim3(1,32,2),256,GSMEM>>>(W3, base);
}

extern "C" void kernel_launch(void* const* d_in, const int* in_sizes, int n_in,
                              void* d_out, int out_size)
{
    (void)in_sizes; (void)n_in; (void)out_size;
    const float* x    = (const float*)d_in[0];
    const int*   ei   = (const int*)  d_in[1];
    const float* ew   = (const float*)d_in[2];
    const float* txg  = (const float*)d_in[3];
    const float* Wk   = (const float*)d_in[5];
    const float* W1   = (const float*)d_in[6];
    const float* W2   = (const float*)d_in[7];
    const float* W3   = (const float*)d_in[8];
    const float* linW = (const float*)d_in[9];
    float* out = (float*)d_out;
    const int* row = ei;
    const int* col = ei + NE;

    cudaFuncSetAttribute(k_pgemm<0>, cudaFuncAttributeMaxDynamicSharedMemorySize, GSMEM);
    cudaFuncSetAttribute(k_pgemm<2>, cudaFuncAttributeMaxDynamicSharedMemorySize, GSMEM);
    cudaFuncSetAttribute(k_pgemm<3>, cudaFuncAttributeMaxDynamicSharedMemorySize, GSMEM);
    cudaFuncSetAttribute(k_w2s,       cudaFuncAttributeMaxDynamicSharedMemorySize, GSMEM);
    cudaFuncSetAttribute(k_prep_graph, cudaFuncAttributeMaxDynamicSharedMemorySize, 98304);
    cudaFuncSetAttribute(k_xc_hop2,   cudaFuncAttributeMaxDynamicSharedMemorySize, 81920);

    float *p_xq,*p_qt,*p_P;
    __nv_bfloat16 *p_XP,*p_xcP,*p_aggP,*p_WkP,*p_W1P,*p_LWP,*p_h0P,*p_h1P;
    cudaGetSymbolAddress((void**)&p_xq,   g_xq);
    cudaGetSymbolAddress((void**)&p_qt,   g_qt);
    cudaGetSymbolAddress((void**)&p_P,    g_P);
    cudaGetSymbolAddress((void**)&p_XP,   g_XP);
    cudaGetSymbolAddress((void**)&p_xcP,  g_xcP);
    cudaGetSymbolAddress((void**)&p_aggP, g_aggP);
    cudaGetSymbolAddress((void**)&p_WkP,  g_WkP);
    cudaGetSymbolAddress((void**)&p_W1P,  g_W1P);
    cudaGetSymbolAddress((void**)&p_LWP,  g_LWP);
    cudaGetSymbolAddress((void**)&p_h0P,  g_h0P);
    cudaGetSymbolAddress((void**)&p_h1P,  g_h1P);

    // 1. prep + graph build + hop^2(x)
    k_prep_graph<<<NBATCH + PREP_BLOCKS, 256, 98304>>>(Wk, W1, W2, linW, x, txg,
                                                       row, col, ew, (float4*)p_xq);
    // 2-4. f1 = att(x, xq); f2 = att(x, qt)
    launch_attention(0, p_XP, p_xq, p_qt, W3, p_WkP, p_W1P, p_h0P, p_h1P);
    // 5. edge softmax -> S + agg planes
    k_edge<<<NBATCH,256>>>(x);
    // 6. P[h] = agg @ lin_W[h]
    k_pgemm<0><<<dim3(1,32,2),256,GSMEM>>>(
        p_aggP, 0LL, (long long)NNODES*HD,
        p_LWP, 128LL*128, 2LL*128*128,
        128, 128,
        p_P, (long long)NNODES*HD,
        nullptr, 0LL, 0LL,
        nullptr, nullptr);
    // 7. xc + split + hop^2
    k_xc_hop2<<<NBATCH,256,81920>>>(x, (float4*)p_xq);
    // 8-10. g1 = att(xc, xq2); g2 = att(xc, qt)
    launch_attention(2, p_xcP, p_xq, p_qt, W3, p_WkP, p_W1P, p_h0P, p_h1P);
    // 11. score softmax + top-k + outputs + A2 (stripe-zeroed internally)
    k_topkA2<<<NBATCH,256>>>(x, out);
}

// round 10
// speedup vs baseline: 1.7842x; 1.1506x over previous
#include <cuda_runtime.h>
#include <cuda_bf16.h>
#include <cstdint>

// ---------------- problem constants ----------------
#define NNODES 4096
#define NBATCH 64
#define NPG    64
#define HD     128
#define HD4    32
#define NE     131072
#define EPB    2048
#define KK     52
#define NK     3328
#define NK4    (NK/4)

#define LEN_X  (NK*HD)
#define OFF_A2 (LEN_X)
#define OFF_B  (OFF_A2 + NK*NK)
#define OFF_P  (OFF_B + NK)

// GEMM smem: 2 buffers x (3 A-planes(64 rows) + 3 B-planes(128 rows)) x 20 u32/row
#define ROWU 20
#define PLUA (64*ROWU)           // 1280 u32
#define PLUB (128*ROWU)          // 2560 u32
#define BUFU (3*PLUA + 3*PLUB)   // 11520 u32
#define GSMEM (2*BUFU*4)         // 92160 bytes

// ---------------- scratch ----------------
__device__ float g_A[NBATCH*NPG*NPG];
__device__ float g_Cnt[NBATCH*NPG*NPG];
__device__ float g_S[NBATCH*NPG*NPG];
__device__ float g_xq[NNODES*HD];
__device__ float g_qt[NNODES*HD];
__device__ float g_f[2*NNODES];
__device__ float g_P[2*NNODES*HD];

// bf16 split planes (plane-major), 16B-aligned
__device__ __align__(16) __nv_bfloat16 g_XP  [3*NNODES*HD];
__device__ __align__(16) __nv_bfloat16 g_xcP [3*NNODES*HD];
__device__ __align__(16) __nv_bfloat16 g_aggP[3*NNODES*HD];
__device__ __align__(16) __nv_bfloat16 g_WkP [3*4*128*128];
__device__ __align__(16) __nv_bfloat16 g_W1P [3*4*256*512];
__device__ __align__(16) __nv_bfloat16 g_W2P [3*4*128*256];
__device__ __align__(16) __nv_bfloat16 g_LWP [3*2*128*128];
__device__ __align__(16) __nv_bfloat16 g_h0P [3*2*NNODES*512];
__device__ __align__(16) __nv_bfloat16 g_h1P [3*2*NNODES*256];

__device__ __forceinline__ float lrelu(float v){ return v > 0.f ? v : 0.01f*v; }

__device__ __forceinline__ void split3(float a, unsigned short& h0, unsigned short& h1, unsigned short& h2){
    __nv_bfloat16 b0 = __float2bfloat16(a); float r1 = a - __bfloat162float(b0);
    __nv_bfloat16 b1 = __float2bfloat16(r1); float r2 = r1 - __bfloat162float(b1);
    __nv_bfloat16 b2 = __float2bfloat16(r2);
    h0 = __bfloat16_as_ushort(b0);
    h1 = __bfloat16_as_ushort(b1);
    h2 = __bfloat16_as_ushort(b2);
}
__device__ __forceinline__ void split2pack(float a, float b, uint32_t& p0, uint32_t& p1, uint32_t& p2){
    unsigned short a0,a1,a2,b0,b1,b2;
    split3(a, a0, a1, a2);
    split3(b, b0, b1, b2);
    p0 = (uint32_t)a0 | ((uint32_t)b0 << 16);
    p1 = (uint32_t)a1 | ((uint32_t)b1 << 16);
    p2 = (uint32_t)a2 | ((uint32_t)b2 << 16);
}

__device__ __forceinline__ void mma16816(float* d, const uint32_t* a, const uint32_t* b){
    asm volatile(
        "mma.sync.aligned.m16n8k16.row.col.f32.bf16.bf16.f32 "
        "{%0,%1,%2,%3}, {%4,%5,%6,%7}, {%8,%9}, {%0,%1,%2,%3};"
        : "+f"(d[0]), "+f"(d[1]), "+f"(d[2]), "+f"(d[3])
        : "r"(a[0]), "r"(a[1]), "r"(a[2]), "r"(a[3]), "r"(b[0]), "r"(b[1]));
}

__device__ __forceinline__ void ldm4(uint32_t* r, uint32_t addr){
    asm volatile("ldmatrix.sync.aligned.m8n8.x4.shared.b16 {%0,%1,%2,%3}, [%4];"
        : "=r"(r[0]), "=r"(r[1]), "=r"(r[2]), "=r"(r[3]) : "r"(addr));
}

__device__ __forceinline__ void cpasync16(uint32_t dst, const void* src){
    asm volatile("cp.async.ca.shared.global [%0], [%1], 16;" :: "r"(dst), "l"(src) : "memory");
}
#define CP_COMMIT() asm volatile("cp.async.commit_group;" ::: "memory")
#define CP_WAIT0()  asm volatile("cp.async.wait_group 0;" ::: "memory")

// ---------------- cp.async fill: tile A 64 rows, B 128 rows, 32 k-halfs, 128 threads ----------------
#define ISSUECOPY(AP, aZ, aP, BP, bZ, bP, KTOT, K0, BUFB)                                  \
    _Pragma("unroll")                                                                      \
    for (int p=0; p<3; p++){                                                               \
        _Pragma("unroll")                                                                  \
        for (int it=0; it<2; it++){                                                        \
            int e = t + it*128;                                                            \
            int ar = e >> 2, aq = e & 3;                                                   \
            const __nv_bfloat16* as = (AP) + (size_t)p*(aP) + (size_t)z*(aZ)               \
                + (size_t)(rowBase+ar)*(KTOT) + (K0) + aq*8;                               \
            cpasync16(sbb + (BUFB) + p*(PLUA*4) + ar*80 + aq*16, as);                      \
        }                                                                                  \
        _Pragma("unroll")                                                                  \
        for (int it=0; it<4; it++){                                                        \
            int e = t + it*128;                                                            \
            int br = e >> 2, bq = e & 3;                                                   \
            const __nv_bfloat16* bs = (BP) + (size_t)p*(bP) + (size_t)z*(bZ)               \
                + (size_t)(colBase+br)*(KTOT) + (K0) + bq*8;                               \
            cpasync16(sbb + (BUFB) + (3*PLUA + p*PLUB)*4 + br*80 + bq*16, bs);             \
        }                                                                                  \
    }                                                                                      \
    CP_COMMIT();

// ldmatrix-based MMA stage. BUFB = byte offset of the active buffer.
#define MMACHUNK(BUFB)                                                                     \
    _Pragma("unroll")                                                                      \
    for (int s=0; s<2; s++){                                                               \
        uint32_t bf[3][4][2];                                                              \
        _Pragma("unroll")                                                                  \
        for (int p=0; p<3; p++){                                                           \
            _Pragma("unroll")                                                              \
            for (int pi=0; pi<2; pi++){                                                    \
                uint32_t r4[4];                                                            \
                ldm4(r4, sbb + (BUFB) + (3*PLUA + p*PLUB)*4 + bRowBase + pi*(16*ROWU*4) + s*32); \
                bf[p][2*pi][0]=r4[0];   bf[p][2*pi][1]=r4[1];                              \
                bf[p][2*pi+1][0]=r4[2]; bf[p][2*pi+1][1]=r4[3];                            \
            }                                                                              \
        }                                                                                  \
        _Pragma("unroll")                                                                  \
        for (int apl=0; apl<3; apl++){                                                     \
            uint32_t af[4][4];                                                             \
            _Pragma("unroll")                                                              \
            for (int mi=0; mi<4; mi++)                                                     \
                ldm4(af[mi], sbb + (BUFB) + apl*(PLUA*4) + aRowBase + mi*(16*ROWU*4) + s*32);\
            int nb = (apl==0)?3:((apl==1)?2:1);                                            \
            _Pragma("unroll")                                                              \
            for (int bpl=0; bpl<3; bpl++){                                                 \
                if (bpl >= nb) break;                                                      \
                _Pragma("unroll")                                                          \
                for (int mi=0; mi<4; mi++)                                                 \
                    _Pragma("unroll")                                                      \
                    for (int ni=0; ni<4; ni++)                                             \
                        mma16816(acc[mi*4+ni], af[mi], bf[bpl][ni]);                       \
            }                                                                              \
        }                                                                                  \
    }

#define GEMM_MAINLOOP(AP, aZ, aP, BP, bZ, bP, KTOT)                                        \
    int chunks = (KTOT) >> 5;                                                              \
    uint32_t sbb;                                                                          \
    asm("{ .reg .u64 tt; cvta.to.shared.u64 tt, %1; cvt.u32.u64 %0, tt; }" : "=r"(sbb) : "l"(smu)); \
    int quad = lane >> 3, qi = lane & 7;                                                   \
    uint32_t aRowBase = (uint32_t)((quad&1)*8 + qi)*(ROWU*4) + (quad>>1)*16;               \
    uint32_t bRowBase = (uint32_t)(warpN + (quad>>1)*8 + qi)*(ROWU*4) + (quad&1)*16;       \
    ISSUECOPY(AP, aZ, aP, BP, bZ, bP, KTOT, 0, 0)                                          \
    CP_WAIT0();                                                                            \
    __syncthreads();                                                                       \
    for (int c = 0; c < chunks; c++){                                                      \
        uint32_t curB = (uint32_t)(c & 1)*(BUFU*4);                                        \
        uint32_t nxtB = (uint32_t)((c + 1) & 1)*(BUFU*4);                                  \
        if (c + 1 < chunks){ ISSUECOPY(AP, aZ, aP, BP, bZ, bP, KTOT, (c+1) << 5, nxtB) }   \
        MMACHUNK(curB)                                                                     \
        if (c + 1 < chunks){ CP_WAIT0(); }                                                 \
        __syncthreads();                                                                   \
    }

// ---------------- pre-split GEMM, tile 64x128, 128 threads, 2 CTAs/SM ----------------
// EPI: 0=fp32 store, 2=lrelu+split planes, 3=h0 concat splits.
template<int EPI>
__global__ void __launch_bounds__(128, 2) k_pgemm(
    const __nv_bfloat16* __restrict__ AP, long long aZ, long long aP,
    const __nv_bfloat16* __restrict__ BP, long long bZ, long long bP,
    int Ktot, int Nc,
    float* __restrict__ Cout, long long cZ,
    __nv_bfloat16* __restrict__ OP, long long oZ, long long oP,
    const float* __restrict__ q0, const float* __restrict__ q1)
{
    extern __shared__ uint32_t smu[];
    int t = threadIdx.x, wid = t >> 5, lane = t & 31;
    int z = blockIdx.z;
    int rowBase = blockIdx.y * 64;
    int colBase = blockIdx.x * 128;
    int warpN = wid * 32;

    float acc[16][4];
#pragma unroll
    for (int i=0;i<16;i++){ acc[i][0]=0.f; acc[i][1]=0.f; acc[i][2]=0.f; acc[i][3]=0.f; }

    GEMM_MAINLOOP(AP, aZ, aP, BP, bZ, bP, Ktot)

#pragma unroll
    for (int mi=0; mi<4; mi++){
#pragma unroll
        for (int ni=0; ni<4; ni++){
            float* d = acc[mi*4+ni];
            int r0 = rowBase + mi*16 + (lane>>2);
            int c0 = colBase + warpN + ni*8 + (lane&3)*2;
            if (EPI == 0){
                float* cp = Cout + (size_t)z*cZ;
                *(float2*)(cp + (size_t)r0*Nc + c0)     = make_float2(d[0], d[1]);
                *(float2*)(cp + (size_t)(r0+8)*Nc + c0) = make_float2(d[2], d[3]);
            } else if (EPI == 2){
#pragma unroll
                for (int qi2=0; qi2<2; qi2++){
                    int row = r0 + qi2*8;
                    float da = lrelu(d[qi2*2]), db = lrelu(d[qi2*2+1]);
                    uint32_t p0,p1,p2;
                    split2pack(da, db, p0, p1, p2);
                    size_t off = (size_t)z*oZ + (size_t)row*Nc + c0;
                    *(uint32_t*)(OP + off)        = p0;
                    *(uint32_t*)(OP + oP + off)   = p1;
                    *(uint32_t*)(OP + 2*oP + off) = p2;
                }
            } else {   // EPI == 3: h0 concat
                const float* q = z ? q1 : q0;
#pragma unroll
                for (int qi2=0; qi2<2; qi2++){
                    int row = r0 + qi2*8;
                    float av = d[qi2*2], bv = d[qi2*2+1];
                    float qa = q[(size_t)row*128 + c0];
                    float qb = q[(size_t)row*128 + c0 + 1];
                    float sa[4] = {av, qa, av-qa, av*qa};
                    float sb[4] = {bv, qb, bv-qb, bv*qb};
#pragma unroll
                    for (int sec=0; sec<4; sec++){
                        uint32_t p0,p1,p2;
                        split2pack(sa[sec], sb[sec], p0, p1, p2);
                        size_t off = (size_t)z*oZ + (size_t)row*512 + sec*128 + c0;
                        *(uint32_t*)(OP + off)        = p0;
                        *(uint32_t*)(OP + oP + off)   = p1;
                        *(uint32_t*)(OP + 2*oP + off) = p2;
                    }
                }
            }
        }
    }
}

// ---------------- W2 GEMM + W3 dot + per-batch softmax (tile 64x128, one batch/block) ----------------
__global__ void __launch_bounds__(128, 2) k_w2s(const float* __restrict__ W3, int base)
{
    extern __shared__ uint32_t smu[];
    __shared__ float sw3[128];
    __shared__ float slog[4][64];
    __shared__ float sl[64];
    __shared__ float sred[64];
    int t = threadIdx.x, wid = t >> 5, lane = t & 31;
    int z = blockIdx.z;
    int rowBase = blockIdx.y * 64;       // = batch*64
    int colBase = 0;
    int warpN = wid * 32;

    if (t < 128) sw3[t] = W3[(size_t)(base+z)*128 + t];

    float acc[16][4];
#pragma unroll
    for (int i=0;i<16;i++){ acc[i][0]=0.f; acc[i][1]=0.f; acc[i][2]=0.f; acc[i][3]=0.f; }

    GEMM_MAINLOOP(g_h1P, (long long)NNODES*256, 2LL*NNODES*256,
                  g_W2P + (size_t)base*128*256, 128LL*256, 4LL*128*256, 256)

    // per-row partial dot with w3 over this warp's 32 columns
#pragma unroll
    for (int mi=0; mi<4; mi++){
        float pr0 = 0.f, pr1 = 0.f;
#pragma unroll
        for (int ni=0; ni<4; ni++){
            float* d = acc[mi*4+ni];
            int c0 = warpN + ni*8 + (lane&3)*2;
            pr0 += sw3[c0]*lrelu(d[0]) + sw3[c0+1]*lrelu(d[1]);
            pr1 += sw3[c0]*lrelu(d[2]) + sw3[c0+1]*lrelu(d[3]);
        }
        pr0 += __shfl_xor_sync(0xffffffffu, pr0, 1);
        pr0 += __shfl_xor_sync(0xffffffffu, pr0, 2);
        pr1 += __shfl_xor_sync(0xffffffffu, pr1, 1);
        pr1 += __shfl_xor_sync(0xffffffffu, pr1, 2);
        if ((lane & 3) == 0){
            int rl = mi*16 + (lane>>2);
            slog[wid][rl]     = pr0;
            slog[wid][rl + 8] = pr1;
        }
    }
    __syncthreads();
    if (t < 64){
        float v = slog[0][t] + slog[1][t] + slog[2][t] + slog[3][t];
        v = lrelu(v);
        sl[t] = v; sred[t] = v;
    }
    __syncthreads();
    for (int o=32; o>0; o>>=1){ if (t<o) sred[t] = fmaxf(sred[t], sred[t+o]); __syncthreads(); }
    float m = sred[0];
    __syncthreads();
    if (t < 64){ float e = expf(sl[t] - m); sl[t] = e; sred[t] = e; }
    __syncthreads();
    for (int o=32; o>0; o>>=1){ if (t<o) sred[t] += sred[t+o]; __syncthreads(); }
    if (t < 64) g_f[(size_t)z*NNODES + rowBase + t] = sl[t] / sred[0];
}

// ---------------- merged prep + graph ----------------
#define PREP_WK   65536
#define PREP_W1   (PREP_WK + 524288)
#define PREP_W2   (PREP_W1 + 131072)
#define PREP_LW   (PREP_W2 + 32768)
#define PREP_X    (PREP_LW + 524288)
#define PREP_QT   (PREP_X + 524288)
#define PREP_BLOCKS 256

__global__ void k_prep_graph(
    const float* __restrict__ Wk, const float* __restrict__ W1,
    const float* __restrict__ W2, const float* __restrict__ LW,
    const float* __restrict__ x, const float* __restrict__ txg,
    const int* __restrict__ row, const int* __restrict__ col,
    const float* __restrict__ ew, float4* __restrict__ xqout)
{
    int t = threadIdx.x;
    if (blockIdx.x >= NBATCH){
        for (int i = (blockIdx.x - NBATCH)*256 + t; i < PREP_QT; i += PREP_BLOCKS*256){
            unsigned short h0,h1,h2;
            if (i < PREP_WK){
                int z = i >> 14, rem = i & 16383, k = rem >> 7, n = rem & 127;
                split3(Wk[i], h0, h1, h2);
                size_t d = (size_t)(z*128 + n)*128 + k;
                g_WkP[d] = __ushort_as_bfloat16(h0);
                g_WkP[4*16384 + d] = __ushort_as_bfloat16(h1);
                g_WkP[8*16384 + d] = __ushort_as_bfloat16(h2);
            } else if (i < PREP_W1){
                int j = i - PREP_WK;
                int z = j >> 17, rem = j & 131071, k = rem >> 8, n = rem & 255;
                split3(W1[j], h0, h1, h2);
                size_t d = (size_t)(z*256 + n)*512 + k;
                g_W1P[d] = __ushort_as_bfloat16(h0);
                g_W1P[4*131072 + d] = __ushort_as_bfloat16(h1);
                g_W1P[(size_t)8*131072 + d] = __ushort_as_bfloat16(h2);
            } else if (i < PREP_W2){
                int j = i - PREP_W1;
                int z = j >> 15, rem = j & 32767, k = rem >> 7, n = rem & 127;
                split3(W2[j], h0, h1, h2);
                size_t d = (size_t)(z*128 + n)*256 + k;
                g_W2P[d] = __ushort_as_bfloat16(h0);
                g_W2P[4*32768 + d] = __ushort_as_bfloat16(h1);
                g_W2P[8*32768 + d] = __ushort_as_bfloat16(h2);
            } else if (i < PREP_LW){
                int j = i - PREP_W2;
                int z = j >> 14, rem = j & 16383, k = rem >> 7, n = rem & 127;
                split3(LW[j], h0, h1, h2);
                size_t d = (size_t)(z*128 + n)*128 + k;
                g_LWP[d] = __ushort_as_bfloat16(h0);
                g_LWP[2*16384 + d] = __ushort_as_bfloat16(h1);
                g_LWP[4*16384 + d] = __ushort_as_bfloat16(h2);
            } else if (i < PREP_X){
                int j = i - PREP_LW;
                split3(x[j], h0, h1, h2);
                g_XP[j] = __ushort_as_bfloat16(h0);
                g_XP[NNODES*HD + j] = __ushort_as_bfloat16(h1);
                g_XP[2*NNODES*HD + j] = __ushort_as_bfloat16(h2);
            } else {
                int j = i - PREP_X;
                g_qt[j] = txg[((j >> 13) << 7) | (j & 127)];
            }
        }
        return;
    }
    extern __shared__ float sh[];
    float* sA   = sh;
    float* sCnt = sh + 4096;
    float* sx   = sh + 8192;
    float* stmp = sh + 16384;
    __shared__ float sdeg[64];
    int b = blockIdx.x;
    for (int i=t; i<4096; i+=256){ sA[i]=0.f; sCnt[i]=0.f; }
    if (t < 64) sdeg[t] = 1.0f;
    __syncthreads();
    const int* er = row + b*EPB;
    const int* ec = col + b*EPB;
    const float* w = ew + b*EPB;
    for (int i=t; i<EPB; i+=256) atomicAdd(&sdeg[ec[i]&63], w[i]);
    __syncthreads();
    if (t < 64) sdeg[t] = rsqrtf(sdeg[t]);
    __syncthreads();
    for (int i=t; i<EPB; i+=256){
        int r = er[i]&63, c = ec[i]&63;
        atomicAdd(&sA[r*64+c], sdeg[r]*w[i]*sdeg[c]);
        atomicAdd(&sCnt[r*64+c], 1.0f);
    }
    if (t < 64){
        atomicAdd(&sA[t*65], sdeg[t]*sdeg[t]);
        atomicAdd(&sCnt[t*65], 1.0f);
    }
    __syncthreads();
    for (int i=t; i<4096; i+=256){ g_A[b*4096+i] = sA[i]; g_Cnt[b*4096+i] = sCnt[i]; }
    float4* sx4 = (float4*)sx;
    const float4* gx4 = (const float4*)(x + (size_t)b*8192);
    for (int i=t; i<2048; i+=256) sx4[i] = gx4[i];
    __syncthreads();
    int tx = t & 31, ty = t >> 5;
    float4* st4 = (float4*)stmp;
    for (int cc=0; cc<8; cc++){
        int c = ty*8+cc;
        float4 acc = make_float4(0.f,0.f,0.f,0.f);
        for (int r=0; r<64; r++){
            float a = sA[r*64+c];
            float4 v = sx4[r*32+tx];
            acc.x += a*v.x; acc.y += a*v.y; acc.z += a*v.z; acc.w += a*v.w;
        }
        st4[c*32+tx] = acc;
    }
    __syncthreads();
    for (int cc=0; cc<8; cc++){
        int c = ty*8+cc;
        float4 acc = make_float4(0.f,0.f,0.f,0.f);
        for (int r=0; r<64; r++){
            float a = sA[r*64+c];
            float4 v = st4[r*32+tx];
            acc.x += a*v.x; acc.y += a*v.y; acc.z += a*v.z; acc.w += a*v.w;
        }
        xqout[(b*64+c)*32 + tx] = acc;
    }
}

// ---------------- edge softmax + S + agg planes ----------------
__global__ void k_edge(const float* __restrict__ x){
    int b = blockIdx.x, t = threadIdx.x;
    __shared__ float sC[NPG*NPG];
    __shared__ float sL[NPG*NPG];
    __shared__ float sf1[NPG], sf2[NPG], sm_[NPG], sden[NPG];
    for (int i=t; i<NPG*NPG; i+=256) sC[i] = g_Cnt[b*NPG*NPG+i];
    if (t < NPG){ sf1[t] = g_f[b*NPG+t]; sf2[t] = g_f[NNODES + b*NPG+t]; }
    __syncthreads();
    for (int i=t; i<NPG*NPG; i+=256){
        int r = i>>6, c = i&63;
        sL[i] = (sC[i] > 0.f) ? lrelu(sf1[c] + sf2[r]) : -1e30f;
    }
    __syncthreads();
    if (t < NPG){
        float m = -1e30f;
        for (int r=0; r<NPG; r++) m = fmaxf(m, sL[r*NPG+t]);
        float den = 0.f;
        for (int r=0; r<NPG; r++){
            float cc = sC[r*NPG+t];
            if (cc > 0.f) den += cc*expf(sL[r*NPG+t]-m);
        }
        sm_[t] = m; sden[t] = den;
    }
    __syncthreads();
    for (int i=t; i<NPG*NPG; i+=256){
        int c = i & 63;
        float cc = sC[i];
        float s = (cc > 0.f) ? cc*expf(sL[i]-sm_[c])/sden[c] : 0.f;
        sL[i] = s;
        g_S[b*NPG*NPG+i] = s;
    }
    __syncthreads();
    const float4* X4 = (const float4*)x;
    int tx = t & 31, ty = t >> 5;
    for (int cc=0; cc<8; cc++){
        int c = ty*8+cc;
        float4 acc = make_float4(0.f,0.f,0.f,0.f);
        for (int r=0; r<NPG; r++){
            float s = sL[r*NPG+c];
            float4 v = X4[(b*NPG+r)*HD4 + tx];
            acc.x += s*v.x; acc.y += s*v.y; acc.z += s*v.z; acc.w += s*v.w;
        }
        uint32_t pxy0,pxy1,pxy2, pzw0,pzw1,pzw2;
        split2pack(acc.x, acc.y, pxy0, pxy1, pxy2);
        split2pack(acc.z, acc.w, pzw0, pzw1, pzw2);
        size_t base = (size_t)(b*64+c)*128 + tx*4;
        *(uint32_t*)(g_aggP + base)                    = pxy0;
        *(uint32_t*)(g_aggP + base + 2)                = pzw0;
        *(uint32_t*)(g_aggP + NNODES*HD + base)        = pxy1;
        *(uint32_t*)(g_aggP + NNODES*HD + base + 2)    = pzw1;
        *(uint32_t*)(g_aggP + 2*NNODES*HD + base)      = pxy2;
        *(uint32_t*)(g_aggP + 2*NNODES*HD + base + 2)  = pzw2;
    }
}

// ---------------- xc compute + split + hop + hop (merged) ----------------
__global__ void k_xc_hop2(const float* __restrict__ x, float4* __restrict__ xqout){
    extern __shared__ float sh[];
    float* sxc  = sh;
    float* sAm  = sh + 8192;
    float* stmp = sh + 12288;
    int b = blockIdx.x, t = threadIdx.x;
    for (int i=t; i<4096; i+=256) sAm[i] = g_A[b*4096+i];
    for (int i=t; i<4096; i+=256){
        int idx2 = i*2;
        size_t gi = (size_t)b*8192 + idx2;
        float x0 = x[gi], x1 = x[gi+1];
        float p00 = g_P[gi], p01 = g_P[gi+1];
        float p10 = g_P[NNODES*HD + gi], p11 = g_P[NNODES*HD + gi+1];
        float v0 = 0.5f*(lrelu(x0+p00) + lrelu(x0+p10));
        float v1 = 0.5f*(lrelu(x1+p01) + lrelu(x1+p11));
        sxc[idx2] = v0; sxc[idx2+1] = v1;
        uint32_t q0,q1,q2;
        split2pack(v0, v1, q0, q1, q2);
        *(uint32_t*)(g_xcP + gi)                = q0;
        *(uint32_t*)(g_xcP + NNODES*HD + gi)    = q1;
        *(uint32_t*)(g_xcP + 2*NNODES*HD + gi)  = q2;
    }
    __syncthreads();
    int tx = t & 31, ty = t >> 5;
    const float4* sx4 = (const float4*)sxc;
    float4* st4 = (float4*)stmp;
    for (int cc=0; cc<8; cc++){
        int c = ty*8+cc;
        float4 acc = make_float4(0.f,0.f,0.f,0.f);
        for (int r=0; r<NPG; r++){
            float a = sAm[r*NPG+c];
            float4 v = sx4[r*32 + tx];
            acc.x += a*v.x; acc.y += a*v.y; acc.z += a*v.z; acc.w += a*v.w;
        }
        st4[c*32+tx] = acc;
    }
    __syncthreads();
    for (int cc=0; cc<8; cc++){
        int c = ty*8+cc;
        float4 acc = make_float4(0.f,0.f,0.f,0.f);
        for (int r=0; r<NPG; r++){
            float a = sAm[r*NPG+c];
            float4 v = st4[r*32 + tx];
            acc.x += a*v.x; acc.y += a*v.y; acc.z += a*v.z; acc.w += a*v.w;
        }
        xqout[(b*64+c)*32 + tx] = acc;
    }
}

// ---------------- score softmax + top-k + x_out/batch/perm + A2 stripe (merged) ----------------
__global__ void k_topkA2(const float* __restrict__ x, float* __restrict__ out){
    __shared__ float sA[NPG*NPG];
    __shared__ float sS[NPG*NPG];
    __shared__ float sU[NPG*KK];
    __shared__ float s[64];
    __shared__ float red[64];
    __shared__ int lp[KK];
    int b = blockIdx.x, t = threadIdx.x;
    if (t < 64){ float v = g_f[b*64+t] + g_f[NNODES + b*64+t]; s[t] = v; red[t] = v; }
    __syncthreads();
    for (int o=32; o>0; o>>=1){ if (t<o) red[t] = fmaxf(red[t], red[t+o]); __syncthreads(); }
    float m = red[0];
    __syncthreads();
    if (t < 64){ float e = expf(s[t] - m); s[t] = e; red[t] = e; }
    __syncthreads();
    for (int o=32; o>0; o>>=1){ if (t<o) red[t] += red[t+o]; __syncthreads(); }
    float den = red[0];
    __syncthreads();
    if (t < 64) s[t] = s[t] / den;
    __syncthreads();
    if (t < 64){
        float v = s[t];
        int rank = 0;
        for (int j=0; j<64; j++){
            float u = s[j];
            rank += (u > v) || (u == v && j < t);
        }
        if (rank < KK){
            lp[rank] = t;
            out[OFF_B + b*KK+rank] = (float)b;
            out[OFF_P + b*KK+rank] = (float)(b*64+t);
        }
    }
    __syncthreads();
    {
        const float4* x4 = (const float4*)x;
        float4* o4 = (float4*)out;
        for (int i=t; i<KK*32; i+=256){
            int r = i >> 5, f = i & 31;
            int p = lp[r];
            float sc = s[p];
            float4 v = x4[(b*64+p)*32 + f];
            o4[(size_t)(b*KK+r)*32 + f] = make_float4(v.x*sc, v.y*sc, v.z*sc, v.w*sc);
        }
    }
    {
        float4 z4 = make_float4(0.f,0.f,0.f,0.f);
        float4* a4 = (float4*)(out + OFF_A2);
        for (int idx=t; idx<KK*NK4; idx+=256){
            int i2 = idx / NK4, c4 = idx - i2*NK4;
            a4[(size_t)(b*KK+i2)*NK4 + c4] = z4;
        }
    }
    for (int i=t; i<NPG*NPG; i+=256){ sA[i] = g_A[b*NPG*NPG+i]; sS[i] = g_S[b*NPG*NPG+i]; }
    __syncthreads();
    for (int idx=t; idx<NPG*KK; idx+=256){
        int r = idx / KK, j = idx - r*KK;
        int pj = lp[j];
        float acc = 0.f;
        for (int c=0; c<NPG; c++) acc += sA[r*NPG+c]*sS[c*NPG+pj];
        sU[idx] = acc;
    }
    __syncthreads();
    for (int idx=t; idx<KK*KK; idx+=256){
        int i2 = idx / KK, j = idx - i2*KK;
        int pi = lp[i2];
        float acc = 0.f;
        for (int r=0; r<NPG; r++) acc += sS[r*NPG+pi]*sU[r*KK+j];
        float v = (i2 == j) ? 1.0f : acc;
        out[(size_t)OFF_A2 + (size_t)(b*KK+i2)*NK + (b*KK+j)] = v;
    }
}

// ---------------- host ----------------
static void launch_attention(int base,
                             const __nv_bfloat16* kvP,
                             const float* q0, const float* q1,
                             const float* W3,
                             __nv_bfloat16* wkP, __nv_bfloat16* w1P,
                             __nv_bfloat16* h0P, __nv_bfloat16* h1P)
{
    k_pgemm<3><<<dim3(1,64,2),128,GSMEM>>>(
        kvP, 0LL, (long long)NNODES*HD,
        wkP + (size_t)base*128*128, 128LL*128, 4LL*128*128,
        128, 128,
        nullptr, 0LL,
        h0P, (long long)NNODES*512, 2LL*NNODES*512,
        q0, q1);
    k_pgemm<2><<<dim3(2,64,2),128,GSMEM>>>(
        h0P, (long long)NNODES*512, 2LL*NNODES*512,
        w1P + (size_t)base*256*512, 256LL*512, 4LL*256*512,
        512, 256,
        nullptr, 0LL,
        h1P, (long long)NNODES*256, 2LL*NNODES*256,
        nullptr, nullptr);
    k_w2s<<<dim3(1,64,2),128,GSMEM>>>(W3, base);
}

extern "C" void kernel_launch(void* const* d_in, const int* in_sizes, int n_in,
                              void* d_out, int out_size)
{
    (void)in_sizes; (void)n_in; (void)out_size;
    const float* x    = (const float*)d_in[0];
    const int*   ei   = (const int*)  d_in[1];
    const float* ew   = (const float*)d_in[2];
    const float* txg  = (const float*)d_in[3];
    const float* Wk   = (const float*)d_in[5];
    const float* W1   = (const float*)d_in[6];
    const float* W2   = (const float*)d_in[7];
    const float* W3   = (const float*)d_in[8];
    const float* linW = (const float*)d_in[9];
    float* out = (float*)d_out;
    const int* row = ei;
    const int* col = ei + NE;

    cudaFuncSetAttribute(k_pgemm<0>, cudaFuncAttributeMaxDynamicSharedMemorySize, GSMEM);
    cudaFuncSetAttribute(k_pgemm<2>, cudaFuncAttributeMaxDynamicSharedMemorySize, GSMEM);
    cudaFuncSetAttribute(k_pgemm<3>, cudaFuncAttributeMaxDynamicSharedMemorySize, GSMEM);
    cudaFuncSetAttribute(k_w2s,       cudaFuncAttributeMaxDynamicSharedMemorySize, GSMEM);
    cudaFuncSetAttribute(k_prep_graph, cudaFuncAttributeMaxDynamicSharedMemorySize, 98304);
    cudaFuncSetAttribute(k_xc_hop2,   cudaFuncAttributeMaxDynamicSharedMemorySize, 81920);

    float *p_xq,*p_qt,*p_P;
    __nv_bfloat16 *p_XP,*p_xcP,*p_aggP,*p_WkP,*p_W1P,*p_LWP,*p_h0P,*p_h1P;
    cudaGetSymbolAddress((void**)&p_xq,   g_xq);
    cudaGetSymbolAddress((void**)&p_qt,   g_qt);
    cudaGetSymbolAddress((void**)&p_P,    g_P);
    cudaGetSymbolAddress((void**)&p_XP,   g_XP);
    cudaGetSymbolAddress((void**)&p_xcP,  g_xcP);
    cudaGetSymbolAddress((void**)&p_aggP, g_aggP);
    cudaGetSymbolAddress((void**)&p_WkP,  g_WkP);
    cudaGetSymbolAddress((void**)&p_W1P,  g_W1P);
    cudaGetSymbolAddress((void**)&p_LWP,  g_LWP);
    cudaGetSymbolAddress((void**)&p_h0P,  g_h0P);
    cudaGetSymbolAddress((void**)&p_h1P,  g_h1P);

    // 1. prep + graph build + hop^2(x)
    k_prep_graph<<<NBATCH + PREP_BLOCKS, 256, 98304>>>(Wk, W1, W2, linW, x, txg,
                                                       row, col, ew, (float4*)p_xq);
    // 2-4. f1 = att(x, xq); f2 = att(x, qt)
    launch_attention(0, p_XP, p_xq, p_qt, W3, p_WkP, p_W1P, p_h0P, p_h1P);
    // 5. edge softmax -> S + agg planes
    k_edge<<<NBATCH,256>>>(x);
    // 6. P[h] = agg @ lin_W[h]
    k_pgemm<0><<<dim3(1,64,2),128,GSMEM>>>(
        p_aggP, 0LL, (long long)NNODES*HD,
        p_LWP, 128LL*128, 2LL*128*128,
        128, 128,
        p_P, (long long)NNODES*HD,
        nullptr, 0LL, 0LL,
        nullptr, nullptr);
    // 7. xc + split + hop^2
    k_xc_hop2<<<NBATCH,256,81920>>>(x, (float4*)p_xq);
    // 8-10. g1 = att(xc, xq2); g2 = att(xc, qt)
    launch_attention(2, p_xcP, p_xq, p_qt, W3, p_WkP, p_W1P, p_h0P, p_h1P);
    // 11. score softmax + top-k + outputs + A2
    k_topkA2<<<NBATCH,256>>>(x, out);
}